// round 7
// baseline (speedup 1.0000x reference)
#include <cuda_runtime.h>
#include <cstdint>

#ifndef JAX_BITS_MODE
#define JAX_BITS_MODE 0   // 0: partitionable (uniform fold=x0^x1, split=full block); 1: legacy halves
#endif

#define ROWS      131072
#define NA        64
#define NH1       128
#define NH2       64
#define NCF       10
#define TILE_ROWS 64
#define RPW       8
#define NTHREADS  256
#define NTILES    (ROWS / TILE_ROWS)
#define HALF_ELEMS ((unsigned)ROWS * NA / 2u)

struct CfKeys { unsigned a[NCF]; unsigned b[NCF]; };

__host__ __device__ __forceinline__ unsigned rotl32(unsigned x, int r) {
#if defined(__CUDA_ARCH__)
    return __funnelshift_l(x, x, r);
#else
    return (x << r) | (x >> (32 - r));
#endif
}

__host__ __device__ __forceinline__ void tf2x32(unsigned k0, unsigned k1,
                                                unsigned &x0, unsigned &x1) {
    unsigned k2 = k0 ^ k1 ^ 0x1BD11BDAu;
    x0 += k0; x1 += k1;
#define TF_R(r) { x0 += x1; x1 = rotl32(x1, (r)); x1 ^= x0; }
    TF_R(13) TF_R(15) TF_R(26) TF_R(6)
    x0 += k1; x1 += k2 + 1u;
    TF_R(17) TF_R(29) TF_R(16) TF_R(24)
    x0 += k2; x1 += k0 + 2u;
    TF_R(13) TF_R(15) TF_R(26) TF_R(6)
    x0 += k0; x1 += k1 + 3u;
    TF_R(17) TF_R(29) TF_R(16) TF_R(24)
    x0 += k1; x1 += k2 + 4u;
    TF_R(13) TF_R(15) TF_R(26) TF_R(6)
    x0 += k2; x1 += k0 + 5u;
#undef TF_R
}

__device__ __forceinline__ float cf_uniform(unsigned ka, unsigned kb, unsigned e) {
    unsigned bits;
#if JAX_BITS_MODE == 0
    unsigned x0 = 0u, x1 = e;
    tf2x32(ka, kb, x0, x1);
    bits = x0 ^ x1;
#else
    unsigned x0, x1;
    if (e < HALF_ELEMS) { x0 = e; x1 = e + HALF_ELEMS; tf2x32(ka, kb, x0, x1); bits = x0; }
    else                { x0 = e - HALF_ELEMS; x1 = e; tf2x32(ka, kb, x0, x1); bits = x1; }
#endif
    return __uint_as_float((bits >> 9) | 0x3f800000u) - 1.0f;
}

struct __align__(16) SmemLayout {
    float w1a[NA][NH1];
    float w2[NH1][NH2];
    float w3[NH2][NA];
    float b1[NH1];
    float b2[NH2];
    float b3[NA];
    float obs_c[TILE_ROWS][64];
    float w1o_c[64][NH1];
    float act_s[TILE_ROWS][NA];
    float h1_s[TILE_ROWS][NH1];
    float h2_s[TILE_ROWS][NA];
};

#define FMA_BLOCK(ACC, OV, WA, WB, WC, WD)  \
    ACC[0] = fmaf(OV.x, WA.x, ACC[0]);      \
    ACC[1] = fmaf(OV.x, WA.y, ACC[1]);      \
    ACC[2] = fmaf(OV.x, WA.z, ACC[2]);      \
    ACC[3] = fmaf(OV.x, WA.w, ACC[3]);      \
    ACC[0] = fmaf(OV.y, WB.x, ACC[0]);      \
    ACC[1] = fmaf(OV.y, WB.y, ACC[1]);      \
    ACC[2] = fmaf(OV.y, WB.z, ACC[2]);      \
    ACC[3] = fmaf(OV.y, WB.w, ACC[3]);      \
    ACC[0] = fmaf(OV.z, WC.x, ACC[0]);      \
    ACC[1] = fmaf(OV.z, WC.y, ACC[1]);      \
    ACC[2] = fmaf(OV.z, WC.z, ACC[2]);      \
    ACC[3] = fmaf(OV.z, WC.w, ACC[3]);      \
    ACC[0] = fmaf(OV.w, WD.x, ACC[0]);      \
    ACC[1] = fmaf(OV.w, WD.y, ACC[1]);      \
    ACC[2] = fmaf(OV.w, WD.z, ACC[2]);      \
    ACC[3] = fmaf(OV.w, WD.w, ACC[3]);

extern __shared__ __align__(128) char smem_raw[];

__global__ void __launch_bounds__(NTHREADS)
ecm_kernel(const float* __restrict__ obs, const float* __restrict__ actions,
           const float* __restrict__ W1,  const float* __restrict__ b1,
           const float* __restrict__ W2,  const float* __restrict__ b2,
           const float* __restrict__ W3,  const float* __restrict__ b3,
           float* __restrict__ out, CfKeys keys)
{
    SmemLayout* s = reinterpret_cast<SmemLayout*>(smem_raw);
    const int tid  = threadIdx.x;
    const int w    = tid >> 5;
    const int lane = tid & 31;
    const int rows0 = blockIdx.x * TILE_ROWS;
    const int lr0   = w * RPW;

    // resident weights
    {
        const float4* W1f = (const float4*)W1;
        float4* d1 = (float4*)&s->w1a[0][0];
        for (int i = tid; i < NA * NH1 / 4; i += NTHREADS) d1[i] = W1f[256 * 32 + i];
        const float4* W2f = (const float4*)W2;
        float4* d2 = (float4*)&s->w2[0][0];
        for (int i = tid; i < NH1 * NH2 / 4; i += NTHREADS) d2[i] = W2f[i];
        const float4* W3f = (const float4*)W3;
        float4* d3 = (float4*)&s->w3[0][0];
        for (int i = tid; i < NH2 * NA / 4; i += NTHREADS) d3[i] = W3f[i];
        for (int i = tid; i < NH1; i += NTHREADS) s->b1[i] = b1[i];
        for (int i = tid; i < NH2; i += NTHREADS) s->b2[i] = b2[i];
        for (int i = tid; i < NA;  i += NTHREADS) s->b3[i] = b3[i];
    }

    // phase A: h1_base = b1 + obs @ W1_obs
    float h1b[RPW][4];
    __syncthreads();
    {
        float4 bv = *(const float4*)&s->b1[lane * 4];
        #pragma unroll
        for (int r = 0; r < RPW; ++r) {
            h1b[r][0] = bv.x; h1b[r][1] = bv.y; h1b[r][2] = bv.z; h1b[r][3] = bv.w;
        }
    }
    const float4* obsf = (const float4*)obs;
    const float4* W1f  = (const float4*)W1;
    for (int kc = 0; kc < 4; ++kc) {
        __syncthreads();
        #pragma unroll
        for (int i = 0; i < 4; ++i) {
            int fl = i * NTHREADS + tid;
            ((float4*)s->obs_c)[fl] = obsf[(size_t)(rows0 + (fl >> 4)) * 64 + kc * 16 + (fl & 15)];
        }
        #pragma unroll
        for (int i = 0; i < 8; ++i) {
            int fl = i * NTHREADS + tid;
            ((float4*)s->w1o_c)[fl] = W1f[kc * 2048 + fl];
        }
        __syncthreads();
        #pragma unroll 2
        for (int k4 = 0; k4 < 16; ++k4) {
            float4 wa = *(const float4*)&s->w1o_c[k4 * 4 + 0][lane * 4];
            float4 wb = *(const float4*)&s->w1o_c[k4 * 4 + 1][lane * 4];
            float4 wc = *(const float4*)&s->w1o_c[k4 * 4 + 2][lane * 4];
            float4 wd = *(const float4*)&s->w1o_c[k4 * 4 + 3][lane * 4];
            #pragma unroll
            for (int r = 0; r < RPW; ++r) {
                float4 ov = *(const float4*)&s->obs_c[lr0 + r][k4 * 4];
                FMA_BLOCK(h1b[r], ov, wa, wb, wc, wd)
            }
        }
    }

    // stage true actions
    __syncthreads();
    {
        const float4* actf = (const float4*)actions;
        #pragma unroll
        for (int i = 0; i < 4; ++i) {
            int fl = i * NTHREADS + tid;
            ((float4*)s->act_s)[fl] = actf[(size_t)rows0 * 16 + fl];
        }
    }
    __syncthreads();

    float pw[RPW][2], po[RPW][2];
    for (int pass = 0; pass < 12; ++pass) {
        if (pass >= 2) {
            unsigned ka = keys.a[pass - 2], kb = keys.b[pass - 2];
            __syncthreads();
            #pragma unroll 2
            for (int i = 0; i < 16; ++i) {
                int fl = i * NTHREADS + tid;
                ((float*)s->act_s)[fl] = cf_uniform(ka, kb, (unsigned)(rows0 * NA + fl));
            }
            __syncthreads();
        }

        // layer 1
        float a1[RPW][4];
        #pragma unroll
        for (int r = 0; r < RPW; ++r) {
            a1[r][0] = h1b[r][0]; a1[r][1] = h1b[r][1];
            a1[r][2] = h1b[r][2]; a1[r][3] = h1b[r][3];
        }
        if (pass != 1) {
            #pragma unroll 2
            for (int k4 = 0; k4 < 16; ++k4) {
                float4 wa = *(const float4*)&s->w1a[k4 * 4 + 0][lane * 4];
                float4 wb = *(const float4*)&s->w1a[k4 * 4 + 1][lane * 4];
                float4 wc = *(const float4*)&s->w1a[k4 * 4 + 2][lane * 4];
                float4 wd = *(const float4*)&s->w1a[k4 * 4 + 3][lane * 4];
                #pragma unroll
                for (int r = 0; r < RPW; ++r) {
                    float4 av = *(const float4*)&s->act_s[lr0 + r][k4 * 4];
                    FMA_BLOCK(a1[r], av, wa, wb, wc, wd)
                }
            }
        }
        #pragma unroll
        for (int r = 0; r < RPW; ++r) {
            float4 hv;
            hv.x = fmaxf(a1[r][0], 0.f); hv.y = fmaxf(a1[r][1], 0.f);
            hv.z = fmaxf(a1[r][2], 0.f); hv.w = fmaxf(a1[r][3], 0.f);
            *(float4*)&s->h1_s[lr0 + r][lane * 4] = hv;
        }
        __syncwarp();

        // layer 2
        float a2[RPW][2];
        {
            float bb0 = s->b2[lane], bb1 = s->b2[lane + 32];
            #pragma unroll
            for (int r = 0; r < RPW; ++r) { a2[r][0] = bb0; a2[r][1] = bb1; }
        }
        #pragma unroll 2
        for (int k4 = 0; k4 < 32; ++k4) {
            int k = k4 * 4;
            float wx0 = s->w2[k + 0][lane], wy0 = s->w2[k + 0][lane + 32];
            float wx1 = s->w2[k + 1][lane], wy1 = s->w2[k + 1][lane + 32];
            float wx2 = s->w2[k + 2][lane], wy2 = s->w2[k + 2][lane + 32];
            float wx3 = s->w2[k + 3][lane], wy3 = s->w2[k + 3][lane + 32];
            #pragma unroll
            for (int r = 0; r < RPW; ++r) {
                float4 hv = *(const float4*)&s->h1_s[lr0 + r][k];
                a2[r][0] = fmaf(hv.x, wx0, a2[r][0]);
                a2[r][0] = fmaf(hv.y, wx1, a2[r][0]);
                a2[r][0] = fmaf(hv.z, wx2, a2[r][0]);
                a2[r][0] = fmaf(hv.w, wx3, a2[r][0]);
                a2[r][1] = fmaf(hv.x, wy0, a2[r][1]);
                a2[r][1] = fmaf(hv.y, wy1, a2[r][1]);
                a2[r][1] = fmaf(hv.z, wy2, a2[r][1]);
                a2[r][1] = fmaf(hv.w, wy3, a2[r][1]);
            }
        }
        #pragma unroll
        for (int r = 0; r < RPW; ++r) {
            s->h2_s[lr0 + r][lane]      = fmaxf(a2[r][0], 0.f);
            s->h2_s[lr0 + r][lane + 32] = fmaxf(a2[r][1], 0.f);
        }
        __syncwarp();

        // layer 3
        float a3[RPW][2];
        {
            float cb0 = s->b3[lane], cb1 = s->b3[lane + 32];
            #pragma unroll
            for (int r = 0; r < RPW; ++r) { a3[r][0] = cb0; a3[r][1] = cb1; }
        }
        #pragma unroll 2
        for (int k4 = 0; k4 < 16; ++k4) {
            int k = k4 * 4;
            float wx0 = s->w3[k + 0][lane], wy0 = s->w3[k + 0][lane + 32];
            float wx1 = s->w3[k + 1][lane], wy1 = s->w3[k + 1][lane + 32];
            float wx2 = s->w3[k + 2][lane], wy2 = s->w3[k + 2][lane + 32];
            float wx3 = s->w3[k + 3][lane], wy3 = s->w3[k + 3][lane + 32];
            #pragma unroll
            for (int r = 0; r < RPW; ++r) {
                float4 hv = *(const float4*)&s->h2_s[lr0 + r][k];
                a3[r][0] = fmaf(hv.x, wx0, a3[r][0]);
                a3[r][0] = fmaf(hv.y, wx1, a3[r][0]);
                a3[r][0] = fmaf(hv.z, wx2, a3[r][0]);
                a3[r][0] = fmaf(hv.w, wx3, a3[r][0]);
                a3[r][1] = fmaf(hv.x, wy0, a3[r][1]);
                a3[r][1] = fmaf(hv.y, wy1, a3[r][1]);
                a3[r][1] = fmaf(hv.z, wy2, a3[r][1]);
                a3[r][1] = fmaf(hv.w, wy3, a3[r][1]);
            }
        }
        if (pass == 0) {
            #pragma unroll
            for (int r = 0; r < RPW; ++r) { pw[r][0] = a3[r][0]; pw[r][1] = a3[r][1]; }
        } else if (pass == 1) {
            #pragma unroll
            for (int r = 0; r < RPW; ++r) { po[r][0] = a3[r][0]; po[r][1] = a3[r][1]; }
        } else {
            #pragma unroll
            for (int r = 0; r < RPW; ++r) { po[r][0] += a3[r][0]; po[r][1] += a3[r][1]; }
        }
    }

    // epilogue: log-softmax + KL, mean over A
    const float inv11 = 1.0f / 11.0f;
    for (int r = 0; r < RPW; ++r) {
        float p0 = pw[r][0], p1 = pw[r][1];
        float q0 = po[r][0] * inv11, q1 = po[r][1] * inv11;

        float mw = fmaxf(p0, p1);
        #pragma unroll
        for (int o = 16; o > 0; o >>= 1) mw = fmaxf(mw, __shfl_xor_sync(0xffffffffu, mw, o));
        float sw = expf(p0 - mw) + expf(p1 - mw);
        #pragma unroll
        for (int o = 16; o > 0; o >>= 1) sw += __shfl_xor_sync(0xffffffffu, sw, o);
        float logZw = mw + logf(sw);

        float mq = fmaxf(q0, q1);
        #pragma unroll
        for (int o = 16; o > 0; o >>= 1) mq = fmaxf(mq, __shfl_xor_sync(0xffffffffu, mq, o));
        float sq = expf(q0 - mq) + expf(q1 - mq);
        #pragma unroll
        for (int o = 16; o > 0; o >>= 1) sq += __shfl_xor_sync(0xffffffffu, sq, o);
        float logZq = mq + logf(sq);

        float lq0 = q0 - logZq, lq1 = q1 - logZq;
        float part = expf(lq0) * (lq0 - (p0 - logZw)) + expf(lq1) * (lq1 - (p1 - logZw));
        #pragma unroll
        for (int o = 16; o > 0; o >>= 1) part += __shfl_xor_sync(0xffffffffu, part, o);

        if (lane == 0) out[rows0 + lr0 + r] = part * (1.0f / 64.0f);
    }
}

static void compute_cf_keys(CfKeys* kk) {
    const unsigned pa = 0u, pb = 42u;   // jax.random.key(42) -> (0, 42)
#if JAX_BITS_MODE == 0
    // partitionable foldlike split (_threefry_split_foldlike):
    // child key j = FULL 2x32 output block of counter (hi=0, lo=j)
    for (unsigned j = 0; j < NCF; ++j) {
        unsigned x0 = 0u, x1 = j;
        tf2x32(pa, pb, x0, x1);
        kk->a[j] = x0;
        kk->b[j] = x1;
    }
#else
    // legacy split: counts 0..19 halved, outputs concatenated, reshape (10,2)
    unsigned bits[2 * NCF];
    for (unsigned i = 0; i < NCF; ++i) {
        unsigned x0 = i, x1 = i + NCF;
        tf2x32(pa, pb, x0, x1);
        bits[i] = x0; bits[i + NCF] = x1;
    }
    for (int j = 0; j < NCF; ++j) { kk->a[j] = bits[2 * j]; kk->b[j] = bits[2 * j + 1]; }
#endif
}

extern "C" void kernel_launch(void* const* d_in, const int* in_sizes, int n_in,
                              void* d_out, int out_size) {
    (void)in_sizes; (void)n_in; (void)out_size;
    const float* obs = (const float*)d_in[0];
    const float* act = (const float*)d_in[1];
    const float* W1  = (const float*)d_in[2];
    const float* b1  = (const float*)d_in[3];
    const float* W2  = (const float*)d_in[4];
    const float* b2  = (const float*)d_in[5];
    const float* W3  = (const float*)d_in[6];
    const float* b3  = (const float*)d_in[7];
    float* out = (float*)d_out;

    CfKeys kk;
    compute_cf_keys(&kk);

    size_t smem = sizeof(SmemLayout);
    cudaFuncSetAttribute(ecm_kernel, cudaFuncAttributeMaxDynamicSharedMemorySize, (int)smem);
    ecm_kernel<<<NTILES, NTHREADS, smem>>>(obs, act, W1, b1, W2, b2, W3, b3, out, kk);
}

// round 9
// speedup vs baseline: 1.0246x; 1.0246x over previous
#include <cuda_runtime.h>
#include <cstdint>

#ifndef JAX_BITS_MODE
#define JAX_BITS_MODE 0
#endif

#define ROWS      131072
#define NA        64
#define NH1       128
#define NH2       64
#define NCF       10
#define TILE_ROWS 64
#define RPW       4
#define NTHREADS  512
#define NTILES    (ROWS / TILE_ROWS)
#define HALF_ELEMS ((unsigned)ROWS * NA / 2u)

struct CfKeys { unsigned a[NCF]; unsigned b[NCF]; };

__host__ __device__ __forceinline__ unsigned rotl32(unsigned x, int r) {
#if defined(__CUDA_ARCH__)
    return __funnelshift_l(x, x, r);
#else
    return (x << r) | (x >> (32 - r));
#endif
}

__host__ __device__ __forceinline__ void tf2x32(unsigned k0, unsigned k1,
                                                unsigned &x0, unsigned &x1) {
    unsigned k2 = k0 ^ k1 ^ 0x1BD11BDAu;
    x0 += k0; x1 += k1;
#define TF_R(r) { x0 += x1; x1 = rotl32(x1, (r)); x1 ^= x0; }
    TF_R(13) TF_R(15) TF_R(26) TF_R(6)
    x0 += k1; x1 += k2 + 1u;
    TF_R(17) TF_R(29) TF_R(16) TF_R(24)
    x0 += k2; x1 += k0 + 2u;
    TF_R(13) TF_R(15) TF_R(26) TF_R(6)
    x0 += k0; x1 += k1 + 3u;
    TF_R(17) TF_R(29) TF_R(16) TF_R(24)
    x0 += k1; x1 += k2 + 4u;
    TF_R(13) TF_R(15) TF_R(26) TF_R(6)
    x0 += k2; x1 += k0 + 5u;
#undef TF_R
}

__device__ __forceinline__ float cf_uniform(unsigned ka, unsigned kb, unsigned e) {
    unsigned bits;
#if JAX_BITS_MODE == 0
    unsigned x0 = 0u, x1 = e;
    tf2x32(ka, kb, x0, x1);
    bits = x0 ^ x1;
#else
    unsigned x0, x1;
    if (e < HALF_ELEMS) { x0 = e; x1 = e + HALF_ELEMS; tf2x32(ka, kb, x0, x1); bits = x0; }
    else                { x0 = e - HALF_ELEMS; x1 = e; tf2x32(ka, kb, x0, x1); bits = x1; }
#endif
    return __uint_as_float((bits >> 9) | 0x3f800000u) - 1.0f;
}

struct __align__(16) SmemLayout {
    float w1a[NA][NH1];
    float w2[NH1][NH2];
    float w3[NH2][NA];
    float b1[NH1];
    float b2[NH2];
    float b3[NA];
    float obs_c[TILE_ROWS][64];
    float w1o_c[64][NH1];
    float act_s[TILE_ROWS][NA];
    float h1_s[TILE_ROWS][NH1];
    float h2_s[TILE_ROWS][NA];
};

#define FMA_BLOCK(ACC, OV, WA, WB, WC, WD)  \
    ACC[0] = fmaf(OV.x, WA.x, ACC[0]);      \
    ACC[1] = fmaf(OV.x, WA.y, ACC[1]);      \
    ACC[2] = fmaf(OV.x, WA.z, ACC[2]);      \
    ACC[3] = fmaf(OV.x, WA.w, ACC[3]);      \
    ACC[0] = fmaf(OV.y, WB.x, ACC[0]);      \
    ACC[1] = fmaf(OV.y, WB.y, ACC[1]);      \
    ACC[2] = fmaf(OV.y, WB.z, ACC[2]);      \
    ACC[3] = fmaf(OV.y, WB.w, ACC[3]);      \
    ACC[0] = fmaf(OV.z, WC.x, ACC[0]);      \
    ACC[1] = fmaf(OV.z, WC.y, ACC[1]);      \
    ACC[2] = fmaf(OV.z, WC.z, ACC[2]);      \
    ACC[3] = fmaf(OV.z, WC.w, ACC[3]);      \
    ACC[0] = fmaf(OV.w, WD.x, ACC[0]);      \
    ACC[1] = fmaf(OV.w, WD.y, ACC[1]);      \
    ACC[2] = fmaf(OV.w, WD.z, ACC[2]);      \
    ACC[3] = fmaf(OV.w, WD.w, ACC[3]);

extern __shared__ __align__(128) char smem_raw[];

__global__ void __launch_bounds__(NTHREADS)
ecm_kernel(const float* __restrict__ obs, const float* __restrict__ actions,
           const float* __restrict__ W1,  const float* __restrict__ b1,
           const float* __restrict__ W2,  const float* __restrict__ b2,
           const float* __restrict__ W3,  const float* __restrict__ b3,
           float* __restrict__ out, CfKeys keys)
{
    SmemLayout* s = reinterpret_cast<SmemLayout*>(smem_raw);
    const int tid  = threadIdx.x;
    const int w    = tid >> 5;
    const int lane = tid & 31;
    const int rows0 = blockIdx.x * TILE_ROWS;
    const int lr0   = w * RPW;          // 16 warps x 4 rows = 64 rows

    // resident weights
    {
        const float4* W1f = (const float4*)W1;
        float4* d1 = (float4*)&s->w1a[0][0];
        for (int i = tid; i < NA * NH1 / 4; i += NTHREADS) d1[i] = W1f[256 * 32 + i];
        const float4* W2f = (const float4*)W2;
        float4* d2 = (float4*)&s->w2[0][0];
        for (int i = tid; i < NH1 * NH2 / 4; i += NTHREADS) d2[i] = W2f[i];
        const float4* W3f = (const float4*)W3;
        float4* d3 = (float4*)&s->w3[0][0];
        for (int i = tid; i < NH2 * NA / 4; i += NTHREADS) d3[i] = W3f[i];
        for (int i = tid; i < NH1; i += NTHREADS) s->b1[i] = b1[i];
        for (int i = tid; i < NH2; i += NTHREADS) s->b2[i] = b2[i];
        for (int i = tid; i < NA;  i += NTHREADS) s->b3[i] = b3[i];
    }

    // phase A: h1_base = b1 + obs @ W1_obs  (shared across all 12 passes)
    float h1b[RPW][4];
    __syncthreads();
    {
        float4 bv = *(const float4*)&s->b1[lane * 4];
        #pragma unroll
        for (int r = 0; r < RPW; ++r) {
            h1b[r][0] = bv.x; h1b[r][1] = bv.y; h1b[r][2] = bv.z; h1b[r][3] = bv.w;
        }
    }
    const float4* obsf = (const float4*)obs;
    const float4* W1f  = (const float4*)W1;
    for (int kc = 0; kc < 4; ++kc) {
        __syncthreads();
        #pragma unroll
        for (int i = 0; i < 2; ++i) {
            int fl = i * NTHREADS + tid;       // 0..1023
            ((float4*)s->obs_c)[fl] = obsf[(size_t)(rows0 + (fl >> 4)) * 64 + kc * 16 + (fl & 15)];
        }
        #pragma unroll
        for (int i = 0; i < 4; ++i) {
            int fl = i * NTHREADS + tid;       // 0..2047
            ((float4*)s->w1o_c)[fl] = W1f[kc * 2048 + fl];
        }
        __syncthreads();
        #pragma unroll 2
        for (int k4 = 0; k4 < 16; ++k4) {
            float4 wa = *(const float4*)&s->w1o_c[k4 * 4 + 0][lane * 4];
            float4 wb = *(const float4*)&s->w1o_c[k4 * 4 + 1][lane * 4];
            float4 wc = *(const float4*)&s->w1o_c[k4 * 4 + 2][lane * 4];
            float4 wd = *(const float4*)&s->w1o_c[k4 * 4 + 3][lane * 4];
            #pragma unroll
            for (int r = 0; r < RPW; ++r) {
                float4 ov = *(const float4*)&s->obs_c[lr0 + r][k4 * 4];
                FMA_BLOCK(h1b[r], ov, wa, wb, wc, wd)
            }
        }
    }

    // stage true actions
    __syncthreads();
    {
        const float4* actf = (const float4*)actions;
        #pragma unroll
        for (int i = 0; i < 2; ++i) {
            int fl = i * NTHREADS + tid;       // 0..1023
            ((float4*)s->act_s)[fl] = actf[(size_t)rows0 * 16 + fl];
        }
    }
    __syncthreads();

    float pw[RPW][2], po[RPW][2];
    for (int pass = 0; pass < 12; ++pass) {
        if (pass >= 2) {
            // per-warp CF generation: warp w fills ONLY its own rows -> no block barrier
            unsigned ka = keys.a[pass - 2], kb = keys.b[pass - 2];
            __syncwarp();                      // done reading previous act_s (this warp's rows)
            unsigned base = (unsigned)(rows0 * NA) + (unsigned)(lr0 * NA) + (unsigned)(lane * 8);
            float v[8];
            #pragma unroll
            for (int i = 0; i < 8; ++i) v[i] = cf_uniform(ka, kb, base + i);
            float* dst = (float*)s->act_s + lr0 * NA + lane * 8;
            *(float4*)(dst)     = make_float4(v[0], v[1], v[2], v[3]);
            *(float4*)(dst + 4) = make_float4(v[4], v[5], v[6], v[7]);
            __syncwarp();
        }

        // layer 1: a1 = relu(h1_base + act @ W1_act)
        float a1[RPW][4];
        #pragma unroll
        for (int r = 0; r < RPW; ++r) {
            a1[r][0] = h1b[r][0]; a1[r][1] = h1b[r][1];
            a1[r][2] = h1b[r][2]; a1[r][3] = h1b[r][3];
        }
        if (pass != 1) {
            #pragma unroll 2
            for (int k4 = 0; k4 < 16; ++k4) {
                float4 wa = *(const float4*)&s->w1a[k4 * 4 + 0][lane * 4];
                float4 wb = *(const float4*)&s->w1a[k4 * 4 + 1][lane * 4];
                float4 wc = *(const float4*)&s->w1a[k4 * 4 + 2][lane * 4];
                float4 wd = *(const float4*)&s->w1a[k4 * 4 + 3][lane * 4];
                #pragma unroll
                for (int r = 0; r < RPW; ++r) {
                    float4 av = *(const float4*)&s->act_s[lr0 + r][k4 * 4];
                    FMA_BLOCK(a1[r], av, wa, wb, wc, wd)
                }
            }
        }
        #pragma unroll
        for (int r = 0; r < RPW; ++r) {
            float4 hv;
            hv.x = fmaxf(a1[r][0], 0.f); hv.y = fmaxf(a1[r][1], 0.f);
            hv.z = fmaxf(a1[r][2], 0.f); hv.w = fmaxf(a1[r][3], 0.f);
            *(float4*)&s->h1_s[lr0 + r][lane * 4] = hv;
        }
        __syncwarp();

        // layer 2: a2 = relu(h1 @ W2 + b2)
        float a2[RPW][2];
        {
            float bb0 = s->b2[lane], bb1 = s->b2[lane + 32];
            #pragma unroll
            for (int r = 0; r < RPW; ++r) { a2[r][0] = bb0; a2[r][1] = bb1; }
        }
        #pragma unroll 2
        for (int k4 = 0; k4 < 32; ++k4) {
            int k = k4 * 4;
            float wx0 = s->w2[k + 0][lane], wy0 = s->w2[k + 0][lane + 32];
            float wx1 = s->w2[k + 1][lane], wy1 = s->w2[k + 1][lane + 32];
            float wx2 = s->w2[k + 2][lane], wy2 = s->w2[k + 2][lane + 32];
            float wx3 = s->w2[k + 3][lane], wy3 = s->w2[k + 3][lane + 32];
            #pragma unroll
            for (int r = 0; r < RPW; ++r) {
                float4 hv = *(const float4*)&s->h1_s[lr0 + r][k];
                a2[r][0] = fmaf(hv.x, wx0, a2[r][0]);
                a2[r][0] = fmaf(hv.y, wx1, a2[r][0]);
                a2[r][0] = fmaf(hv.z, wx2, a2[r][0]);
                a2[r][0] = fmaf(hv.w, wx3, a2[r][0]);
                a2[r][1] = fmaf(hv.x, wy0, a2[r][1]);
                a2[r][1] = fmaf(hv.y, wy1, a2[r][1]);
                a2[r][1] = fmaf(hv.z, wy2, a2[r][1]);
                a2[r][1] = fmaf(hv.w, wy3, a2[r][1]);
            }
        }
        #pragma unroll
        for (int r = 0; r < RPW; ++r) {
            s->h2_s[lr0 + r][lane]      = fmaxf(a2[r][0], 0.f);
            s->h2_s[lr0 + r][lane + 32] = fmaxf(a2[r][1], 0.f);
        }
        __syncwarp();

        // layer 3: a3 = h2 @ W3 + b3
        float a3[RPW][2];
        {
            float cb0 = s->b3[lane], cb1 = s->b3[lane + 32];
            #pragma unroll
            for (int r = 0; r < RPW; ++r) { a3[r][0] = cb0; a3[r][1] = cb1; }
        }
        #pragma unroll 2
        for (int k4 = 0; k4 < 16; ++k4) {
            int k = k4 * 4;
            float wx0 = s->w3[k + 0][lane], wy0 = s->w3[k + 0][lane + 32];
            float wx1 = s->w3[k + 1][lane], wy1 = s->w3[k + 1][lane + 32];
            float wx2 = s->w3[k + 2][lane], wy2 = s->w3[k + 2][lane + 32];
            float wx3 = s->w3[k + 3][lane], wy3 = s->w3[k + 3][lane + 32];
            #pragma unroll
            for (int r = 0; r < RPW; ++r) {
                float4 hv = *(const float4*)&s->h2_s[lr0 + r][k];
                a3[r][0] = fmaf(hv.x, wx0, a3[r][0]);
                a3[r][0] = fmaf(hv.y, wx1, a3[r][0]);
                a3[r][0] = fmaf(hv.z, wx2, a3[r][0]);
                a3[r][0] = fmaf(hv.w, wx3, a3[r][0]);
                a3[r][1] = fmaf(hv.x, wy0, a3[r][1]);
                a3[r][1] = fmaf(hv.y, wy1, a3[r][1]);
                a3[r][1] = fmaf(hv.z, wy2, a3[r][1]);
                a3[r][1] = fmaf(hv.w, wy3, a3[r][1]);
            }
        }
        if (pass == 0) {
            #pragma unroll
            for (int r = 0; r < RPW; ++r) { pw[r][0] = a3[r][0]; pw[r][1] = a3[r][1]; }
        } else if (pass == 1) {
            #pragma unroll
            for (int r = 0; r < RPW; ++r) { po[r][0] = a3[r][0]; po[r][1] = a3[r][1]; }
        } else {
            #pragma unroll
            for (int r = 0; r < RPW; ++r) { po[r][0] += a3[r][0]; po[r][1] += a3[r][1]; }
        }
    }

    // epilogue: log-softmax + KL, mean over A
    const float inv11 = 1.0f / 11.0f;
    for (int r = 0; r < RPW; ++r) {
        float p0 = pw[r][0], p1 = pw[r][1];
        float q0 = po[r][0] * inv11, q1 = po[r][1] * inv11;

        float mw = fmaxf(p0, p1);
        #pragma unroll
        for (int o = 16; o > 0; o >>= 1) mw = fmaxf(mw, __shfl_xor_sync(0xffffffffu, mw, o));
        float sw = expf(p0 - mw) + expf(p1 - mw);
        #pragma unroll
        for (int o = 16; o > 0; o >>= 1) sw += __shfl_xor_sync(0xffffffffu, sw, o);
        float logZw = mw + logf(sw);

        float mq = fmaxf(q0, q1);
        #pragma unroll
        for (int o = 16; o > 0; o >>= 1) mq = fmaxf(mq, __shfl_xor_sync(0xffffffffu, mq, o));
        float sq = expf(q0 - mq) + expf(q1 - mq);
        #pragma unroll
        for (int o = 16; o > 0; o >>= 1) sq += __shfl_xor_sync(0xffffffffu, sq, o);
        float logZq = mq + logf(sq);

        float lq0 = q0 - logZq, lq1 = q1 - logZq;
        float part = expf(lq0) * (lq0 - (p0 - logZw)) + expf(lq1) * (lq1 - (p1 - logZw));
        #pragma unroll
        for (int o = 16; o > 0; o >>= 1) part += __shfl_xor_sync(0xffffffffu, part, o);

        if (lane == 0) out[rows0 + lr0 + r] = part * (1.0f / 64.0f);
    }
}

static void compute_cf_keys(CfKeys* kk) {
    const unsigned pa = 0u, pb = 42u;
#if JAX_BITS_MODE == 0
    for (unsigned j = 0; j < NCF; ++j) {
        unsigned x0 = 0u, x1 = j;
        tf2x32(pa, pb, x0, x1);
        kk->a[j] = x0;
        kk->b[j] = x1;
    }
#else
    unsigned bits[2 * NCF];
    for (unsigned i = 0; i < NCF; ++i) {
        unsigned x0 = i, x1 = i + NCF;
        tf2x32(pa, pb, x0, x1);
        bits[i] = x0; bits[i + NCF] = x1;
    }
    for (int j = 0; j < NCF; ++j) { kk->a[j] = bits[2 * j]; kk->b[j] = bits[2 * j + 1]; }
#endif
}

extern "C" void kernel_launch(void* const* d_in, const int* in_sizes, int n_in,
                              void* d_out, int out_size) {
    (void)in_sizes; (void)n_in; (void)out_size;
    const float* obs = (const float*)d_in[0];
    const float* act = (const float*)d_in[1];
    const float* W1  = (const float*)d_in[2];
    const float* b1  = (const float*)d_in[3];
    const float* W2  = (const float*)d_in[4];
    const float* b2  = (const float*)d_in[5];
    const float* W3  = (const float*)d_in[6];
    const float* b3  = (const float*)d_in[7];
    float* out = (float*)d_out;

    CfKeys kk;
    compute_cf_keys(&kk);

    size_t smem = sizeof(SmemLayout);
    cudaFuncSetAttribute(ecm_kernel, cudaFuncAttributeMaxDynamicSharedMemorySize, (int)smem);
    ecm_kernel<<<NTILES, NTHREADS, smem>>>(obs, act, W1, b1, W2, b2, W3, b3, out, kk);
}

// round 10
// speedup vs baseline: 1.3342x; 1.3022x over previous
#include <cuda_runtime.h>
#include <cstdint>

#ifndef JAX_BITS_MODE
#define JAX_BITS_MODE 0
#endif

#define ROWS      131072
#define NA        64
#define NH1       128
#define NH2       64
#define NCF       10
#define TILE_ROWS 128
#define NPAIRS    4          // row pairs per warp (8 rows/warp)
#define NTHREADS  512
#define NTILES    (ROWS / TILE_ROWS)   // 1024

struct CfKeys { unsigned a[NCF]; unsigned b[NCF]; };

typedef unsigned long long u64;

__host__ __device__ __forceinline__ unsigned rotl32(unsigned x, int r) {
#if defined(__CUDA_ARCH__)
    return __funnelshift_l(x, x, r);
#else
    return (x << r) | (x >> (32 - r));
#endif
}

__host__ __device__ __forceinline__ void tf2x32(unsigned k0, unsigned k1,
                                                unsigned &x0, unsigned &x1) {
    unsigned k2 = k0 ^ k1 ^ 0x1BD11BDAu;
    x0 += k0; x1 += k1;
#define TF_R(r) { x0 += x1; x1 = rotl32(x1, (r)); x1 ^= x0; }
    TF_R(13) TF_R(15) TF_R(26) TF_R(6)
    x0 += k1; x1 += k2 + 1u;
    TF_R(17) TF_R(29) TF_R(16) TF_R(24)
    x0 += k2; x1 += k0 + 2u;
    TF_R(13) TF_R(15) TF_R(26) TF_R(6)
    x0 += k0; x1 += k1 + 3u;
    TF_R(17) TF_R(29) TF_R(16) TF_R(24)
    x0 += k1; x1 += k2 + 4u;
    TF_R(13) TF_R(15) TF_R(26) TF_R(6)
    x0 += k2; x1 += k0 + 5u;
#undef TF_R
}

__device__ __forceinline__ float cf_uniform(unsigned ka, unsigned kb, unsigned e) {
#if JAX_BITS_MODE == 0
    unsigned x0 = 0u, x1 = e;
    tf2x32(ka, kb, x0, x1);
    unsigned bits = x0 ^ x1;
#else
    unsigned x0 = 0u, x1 = e;
    tf2x32(ka, kb, x0, x1);
    unsigned bits = x0 ^ x1;
#endif
    return __uint_as_float((bits >> 9) | 0x3f800000u) - 1.0f;
}

// ---- packed fp32x2 helpers ----
__device__ __forceinline__ u64 dup2(float s) {
    u64 d; asm("mov.b64 %0, {%1, %1};" : "=l"(d) : "f"(s)); return d;
}
__device__ __forceinline__ u64 pk2(float lo, float hi) {
    u64 d; asm("mov.b64 %0, {%1, %2};" : "=l"(d) : "f"(lo), "f"(hi)); return d;
}
__device__ __forceinline__ float2 unpk(u64 v) {
    float2 r; asm("mov.b64 {%0, %1}, %2;" : "=f"(r.x), "=f"(r.y) : "l"(v)); return r;
}
__device__ __forceinline__ void fma2(u64 &d, u64 a, u64 b) {
    asm("fma.rn.f32x2 %0, %1, %2, %0;" : "+l"(d) : "l"(a), "l"(b));
}
__device__ __forceinline__ void add2(u64 &d, u64 a) {
    asm("add.rn.f32x2 %0, %0, %1;" : "+l"(d) : "l"(a));
}

struct __align__(16) SmemLayout {
    float  w1a[NA][NH1];            // 32 KB  (W1 action rows, natural)
    float  w2s[NH1][NH2];           // 32 KB
    float  w3s[NH2][NA];            // 16 KB
    float2 act_p[TILE_ROWS/2][NA];  // 32 KB  paired: {a[2p][k], a[2p+1][k]}
    float  b1[NH1];
    float  b2[NH2];
    float  b3[NA];
    union {
        struct {
            float2 h1p[TILE_ROWS/2][NH1];   // 64 KB paired h1
            float2 h2p[TILE_ROWS/2][NA];    // 32 KB paired h2
        };
        struct {
            float2 obs_p[TILE_ROWS/2][64];  // 32 KB paired obs chunk
            float  w1o[64][NH1];            // 32 KB W1 obs-row chunk
        };
    };
};  // ~209 KB

extern __shared__ __align__(128) char smem_raw[];

// 8 packed FMAs: two k-steps (m.x={r0k,r1k}, m.y={r0k1,r1k1}) x 4 output cols
#define L1_STEP(ACC_P, M, D00, D01, D02, D03, D10, D11, D12, D13) \
    fma2(ACC_P[0], M.x, D00); fma2(ACC_P[1], M.x, D01);           \
    fma2(ACC_P[2], M.x, D02); fma2(ACC_P[3], M.x, D03);           \
    fma2(ACC_P[0], M.y, D10); fma2(ACC_P[1], M.y, D11);           \
    fma2(ACC_P[2], M.y, D12); fma2(ACC_P[3], M.y, D13);

__global__ void __launch_bounds__(NTHREADS)
ecm_kernel(const float* __restrict__ obs, const float* __restrict__ actions,
           const float* __restrict__ W1,  const float* __restrict__ b1,
           const float* __restrict__ W2,  const float* __restrict__ b2,
           const float* __restrict__ W3,  const float* __restrict__ b3,
           float* __restrict__ out, CfKeys keys)
{
    SmemLayout* s = reinterpret_cast<SmemLayout*>(smem_raw);
    const int tid  = threadIdx.x;
    const int w    = tid >> 5;
    const int lane = tid & 31;
    const int rows0 = blockIdx.x * TILE_ROWS;
    const int wp0   = w * NPAIRS;            // first pair owned by this warp

    // ---- resident weights ----
    {
        const float4* W1f = (const float4*)W1;
        float4* d1 = (float4*)&s->w1a[0][0];
        for (int i = tid; i < NA * NH1 / 4; i += NTHREADS) d1[i] = W1f[256 * 32 + i];
        const float4* W2f = (const float4*)W2;
        float4* d2 = (float4*)&s->w2s[0][0];
        for (int i = tid; i < NH1 * NH2 / 4; i += NTHREADS) d2[i] = W2f[i];
        const float4* W3f = (const float4*)W3;
        float4* d3 = (float4*)&s->w3s[0][0];
        for (int i = tid; i < NH2 * NA / 4; i += NTHREADS) d3[i] = W3f[i];
        for (int i = tid; i < NH1; i += NTHREADS) s->b1[i] = b1[i];
        for (int i = tid; i < NH2; i += NTHREADS) s->b2[i] = b2[i];
        for (int i = tid; i < NA;  i += NTHREADS) s->b3[i] = b3[i];
    }
    __syncthreads();

    // ---- phase A: h1_base = b1 + obs @ W1_obs (packed over row pairs) ----
    u64 h1acc[NPAIRS][4];
    {
        u64 bd0 = dup2(s->b1[lane * 4 + 0]);
        u64 bd1 = dup2(s->b1[lane * 4 + 1]);
        u64 bd2 = dup2(s->b1[lane * 4 + 2]);
        u64 bd3 = dup2(s->b1[lane * 4 + 3]);
        #pragma unroll
        for (int p = 0; p < NPAIRS; ++p) {
            h1acc[p][0] = bd0; h1acc[p][1] = bd1; h1acc[p][2] = bd2; h1acc[p][3] = bd3;
        }
    }
    const float4* obsf = (const float4*)obs;
    const float4* actf = (const float4*)actions;
    const float4* W1f  = (const float4*)W1;

    for (int kc = 0; kc < 4; ++kc) {
        __syncthreads();
        // stage paired obs chunk: obs_p[pair][kk] = {obs[r0][kc*64+kk], obs[r1][kc*64+kk]}
        #pragma unroll
        for (int it = 0; it < 2; ++it) {
            int fl = it * NTHREADS + tid;            // 0..1023: pair(6b) x kq(4b)
            int pr = fl >> 4, k0 = (fl & 15) * 4;
            int r0 = rows0 + pr * 2;
            float4 a = obsf[((size_t)r0 * 256 + kc * 64 + k0) >> 2];
            float4 b = obsf[((size_t)(r0 + 1) * 256 + kc * 64 + k0) >> 2];
            *(float4*)&s->obs_p[pr][k0]     = make_float4(a.x, b.x, a.y, b.y);
            *(float4*)&s->obs_p[pr][k0 + 2] = make_float4(a.z, b.z, a.w, b.w);
        }
        // stage W1 obs-row chunk (natural)
        #pragma unroll
        for (int it = 0; it < 4; ++it) {
            int fl = it * NTHREADS + tid;            // 0..2047
            ((float4*)s->w1o)[fl] = W1f[kc * 2048 + fl];
        }
        __syncthreads();
        #pragma unroll 2
        for (int k4 = 0; k4 < 16; ++k4) {
            #pragma unroll
            for (int ke = 0; ke < 4; ke += 2) {
                int k = k4 * 4 + ke;
                float4 wk0 = *(const float4*)&s->w1o[k][lane * 4];
                float4 wk1 = *(const float4*)&s->w1o[k + 1][lane * 4];
                u64 d00 = dup2(wk0.x), d01 = dup2(wk0.y), d02 = dup2(wk0.z), d03 = dup2(wk0.w);
                u64 d10 = dup2(wk1.x), d11 = dup2(wk1.y), d12 = dup2(wk1.z), d13 = dup2(wk1.w);
                #pragma unroll
                for (int p = 0; p < NPAIRS; ++p) {
                    ulonglong2 m = *(const ulonglong2*)&s->obs_p[wp0 + p][k];
                    L1_STEP(h1acc[p], m, d00, d01, d02, d03, d10, d11, d12, d13)
                }
            }
        }
    }

    // ---- stage true actions (paired) ----
    __syncthreads();
    #pragma unroll
    for (int it = 0; it < 2; ++it) {
        int fl = it * NTHREADS + tid;                // 0..1023
        int pr = fl >> 4, k0 = (fl & 15) * 4;
        int r0 = rows0 + pr * 2;
        float4 a = actf[((size_t)r0 * 64 + k0) >> 2];
        float4 b = actf[((size_t)(r0 + 1) * 64 + k0) >> 2];
        *(float4*)&s->act_p[pr][k0]     = make_float4(a.x, b.x, a.y, b.y);
        *(float4*)&s->act_p[pr][k0 + 2] = make_float4(a.z, b.z, a.w, b.w);
    }
    __syncthreads();

    u64 pw[NPAIRS][2], po[NPAIRS][2];

    for (int pass = 0; pass < 12; ++pass) {
        if (pass >= 2) {
            // per-warp CF generation into this warp's own pairs
            unsigned ka = keys.a[pass - 2], kb = keys.b[pass - 2];
            __syncwarp();
            int lp = lane >> 3;                      // 0..3 local pair
            int k0 = (lane & 7) * 8;                 // 8 ks per lane
            int pr = wp0 + lp;
            unsigned e0 = (unsigned)((rows0 + pr * 2) * 64 + k0);
            #pragma unroll
            for (int i = 0; i < 8; i += 2) {
                float v00 = cf_uniform(ka, kb, e0 + i);
                float v10 = cf_uniform(ka, kb, e0 + i + 64);
                float v01 = cf_uniform(ka, kb, e0 + i + 1);
                float v11 = cf_uniform(ka, kb, e0 + i + 65);
                *(float4*)&s->act_p[pr][k0 + i] = make_float4(v00, v10, v01, v11);
            }
            __syncwarp();
        }

        // ---- layer 1: a1 = relu(h1_base + act @ W1_act) ----
        u64 a1[NPAIRS][4];
        #pragma unroll
        for (int p = 0; p < NPAIRS; ++p) {
            a1[p][0] = h1acc[p][0]; a1[p][1] = h1acc[p][1];
            a1[p][2] = h1acc[p][2]; a1[p][3] = h1acc[p][3];
        }
        if (pass != 1) {
            #pragma unroll 2
            for (int k4 = 0; k4 < 16; ++k4) {
                #pragma unroll
                for (int ke = 0; ke < 4; ke += 2) {
                    int k = k4 * 4 + ke;
                    float4 wk0 = *(const float4*)&s->w1a[k][lane * 4];
                    float4 wk1 = *(const float4*)&s->w1a[k + 1][lane * 4];
                    u64 d00 = dup2(wk0.x), d01 = dup2(wk0.y), d02 = dup2(wk0.z), d03 = dup2(wk0.w);
                    u64 d10 = dup2(wk1.x), d11 = dup2(wk1.y), d12 = dup2(wk1.z), d13 = dup2(wk1.w);
                    #pragma unroll
                    for (int p = 0; p < NPAIRS; ++p) {
                        ulonglong2 m = *(const ulonglong2*)&s->act_p[wp0 + p][k];
                        L1_STEP(a1[p], m, d00, d01, d02, d03, d10, d11, d12, d13)
                    }
                }
            }
        }
        // relu + paired store to h1p
        #pragma unroll
        for (int p = 0; p < NPAIRS; ++p) {
            float2 c0 = unpk(a1[p][0]), c1 = unpk(a1[p][1]);
            float2 c2 = unpk(a1[p][2]), c3 = unpk(a1[p][3]);
            *(float4*)&s->h1p[wp0 + p][lane * 4] =
                make_float4(fmaxf(c0.x, 0.f), fmaxf(c0.y, 0.f), fmaxf(c1.x, 0.f), fmaxf(c1.y, 0.f));
            *(float4*)&s->h1p[wp0 + p][lane * 4 + 2] =
                make_float4(fmaxf(c2.x, 0.f), fmaxf(c2.y, 0.f), fmaxf(c3.x, 0.f), fmaxf(c3.y, 0.f));
        }
        __syncwarp();

        // ---- layer 2: a2 = relu(h1 @ W2 + b2), cols (lane, lane+32) ----
        u64 a2[NPAIRS][2];
        {
            u64 db0 = dup2(s->b2[lane]), db1 = dup2(s->b2[lane + 32]);
            #pragma unroll
            for (int p = 0; p < NPAIRS; ++p) { a2[p][0] = db0; a2[p][1] = db1; }
        }
        #pragma unroll 2
        for (int k4 = 0; k4 < 32; ++k4) {
            #pragma unroll
            for (int ke = 0; ke < 4; ke += 2) {
                int k = k4 * 4 + ke;
                u64 dA0 = dup2(s->w2s[k][lane]),     dB0 = dup2(s->w2s[k][lane + 32]);
                u64 dA1 = dup2(s->w2s[k + 1][lane]), dB1 = dup2(s->w2s[k + 1][lane + 32]);
                #pragma unroll
                for (int p = 0; p < NPAIRS; ++p) {
                    ulonglong2 m = *(const ulonglong2*)&s->h1p[wp0 + p][k];
                    fma2(a2[p][0], m.x, dA0); fma2(a2[p][1], m.x, dB0);
                    fma2(a2[p][0], m.y, dA1); fma2(a2[p][1], m.y, dB1);
                }
            }
        }
        #pragma unroll
        for (int p = 0; p < NPAIRS; ++p) {
            float2 v0 = unpk(a2[p][0]), v1 = unpk(a2[p][1]);
            s->h2p[wp0 + p][lane]      = make_float2(fmaxf(v0.x, 0.f), fmaxf(v0.y, 0.f));
            s->h2p[wp0 + p][lane + 32] = make_float2(fmaxf(v1.x, 0.f), fmaxf(v1.y, 0.f));
        }
        __syncwarp();

        // ---- layer 3: a3 = h2 @ W3 + b3 ----
        u64 a3[NPAIRS][2];
        {
            u64 db0 = dup2(s->b3[lane]), db1 = dup2(s->b3[lane + 32]);
            #pragma unroll
            for (int p = 0; p < NPAIRS; ++p) { a3[p][0] = db0; a3[p][1] = db1; }
        }
        #pragma unroll 2
        for (int k4 = 0; k4 < 16; ++k4) {
            #pragma unroll
            for (int ke = 0; ke < 4; ke += 2) {
                int k = k4 * 4 + ke;
                u64 dA0 = dup2(s->w3s[k][lane]),     dB0 = dup2(s->w3s[k][lane + 32]);
                u64 dA1 = dup2(s->w3s[k + 1][lane]), dB1 = dup2(s->w3s[k + 1][lane + 32]);
                #pragma unroll
                for (int p = 0; p < NPAIRS; ++p) {
                    ulonglong2 m = *(const ulonglong2*)&s->h2p[wp0 + p][k];
                    fma2(a3[p][0], m.x, dA0); fma2(a3[p][1], m.x, dB0);
                    fma2(a3[p][0], m.y, dA1); fma2(a3[p][1], m.y, dB1);
                }
            }
        }
        if (pass == 0) {
            #pragma unroll
            for (int p = 0; p < NPAIRS; ++p) { pw[p][0] = a3[p][0]; pw[p][1] = a3[p][1]; }
        } else if (pass == 1) {
            #pragma unroll
            for (int p = 0; p < NPAIRS; ++p) { po[p][0] = a3[p][0]; po[p][1] = a3[p][1]; }
        } else {
            #pragma unroll
            for (int p = 0; p < NPAIRS; ++p) { add2(po[p][0], a3[p][0]); add2(po[p][1], a3[p][1]); }
        }
    }

    // ---- epilogue: log-softmax + KL, mean over A, per row ----
    const float inv11 = 1.0f / 11.0f;
    #pragma unroll
    for (int p = 0; p < NPAIRS; ++p) {
        float2 pwc0 = unpk(pw[p][0]), pwc1 = unpk(pw[p][1]);
        float2 poc0 = unpk(po[p][0]), poc1 = unpk(po[p][1]);
        #pragma unroll
        for (int h = 0; h < 2; ++h) {
            float p0 = h ? pwc0.y : pwc0.x;
            float p1 = h ? pwc1.y : pwc1.x;
            float q0 = (h ? poc0.y : poc0.x) * inv11;
            float q1 = (h ? poc1.y : poc1.x) * inv11;

            float mw = fmaxf(p0, p1);
            #pragma unroll
            for (int o = 16; o > 0; o >>= 1) mw = fmaxf(mw, __shfl_xor_sync(0xffffffffu, mw, o));
            float sw = expf(p0 - mw) + expf(p1 - mw);
            #pragma unroll
            for (int o = 16; o > 0; o >>= 1) sw += __shfl_xor_sync(0xffffffffu, sw, o);
            float logZw = mw + logf(sw);

            float mq = fmaxf(q0, q1);
            #pragma unroll
            for (int o = 16; o > 0; o >>= 1) mq = fmaxf(mq, __shfl_xor_sync(0xffffffffu, mq, o));
            float sq = expf(q0 - mq) + expf(q1 - mq);
            #pragma unroll
            for (int o = 16; o > 0; o >>= 1) sq += __shfl_xor_sync(0xffffffffu, sq, o);
            float logZq = mq + logf(sq);

            float lq0 = q0 - logZq, lq1 = q1 - logZq;
            float part = expf(lq0) * (lq0 - (p0 - logZw)) + expf(lq1) * (lq1 - (p1 - logZw));
            #pragma unroll
            for (int o = 16; o > 0; o >>= 1) part += __shfl_xor_sync(0xffffffffu, part, o);

            if (lane == 0) out[rows0 + (wp0 + p) * 2 + h] = part * (1.0f / 64.0f);
        }
    }
}

static void compute_cf_keys(CfKeys* kk) {
    const unsigned pa = 0u, pb = 42u;
    for (unsigned j = 0; j < NCF; ++j) {
        unsigned x0 = 0u, x1 = j;
        tf2x32(pa, pb, x0, x1);
        kk->a[j] = x0;
        kk->b[j] = x1;
    }
}

extern "C" void kernel_launch(void* const* d_in, const int* in_sizes, int n_in,
                              void* d_out, int out_size) {
    (void)in_sizes; (void)n_in; (void)out_size;
    const float* obs = (const float*)d_in[0];
    const float* act = (const float*)d_in[1];
    const float* W1  = (const float*)d_in[2];
    const float* b1  = (const float*)d_in[3];
    const float* W2  = (const float*)d_in[4];
    const float* b2  = (const float*)d_in[5];
    const float* W3  = (const float*)d_in[6];
    const float* b3  = (const float*)d_in[7];
    float* out = (float*)d_out;

    CfKeys kk;
    compute_cf_keys(&kk);

    size_t smem = sizeof(SmemLayout);
    cudaFuncSetAttribute(ecm_kernel, cudaFuncAttributeMaxDynamicSharedMemorySize, (int)smem);
    ecm_kernel<<<NTILES, NTHREADS, smem>>>(obs, act, W1, b1, W2, b2, W3, b3, out, kk);
}

// round 11
// speedup vs baseline: 1.3349x; 1.0005x over previous
#include <cuda_runtime.h>
#include <cstdint>

#ifndef JAX_BITS_MODE
#define JAX_BITS_MODE 0
#endif

#define ROWS      131072
#define NA        64
#define NH1       128
#define NH2       64
#define NCF       10
#define TILE_ROWS 128
#define NPAIRS    4          // row pairs per warp (8 rows/warp)
#define NTHREADS  512
#define NTILES    (ROWS / TILE_ROWS)   // 1024

struct CfKeys { unsigned a[NCF]; unsigned b[NCF]; };

typedef unsigned long long u64;

__host__ __device__ __forceinline__ unsigned rotl32(unsigned x, int r) {
#if defined(__CUDA_ARCH__)
    return __funnelshift_l(x, x, r);
#else
    return (x << r) | (x >> (32 - r));
#endif
}

__host__ __device__ __forceinline__ void tf2x32(unsigned k0, unsigned k1,
                                                unsigned &x0, unsigned &x1) {
    unsigned k2 = k0 ^ k1 ^ 0x1BD11BDAu;
    x0 += k0; x1 += k1;
#define TF_R(r) { x0 += x1; x1 = rotl32(x1, (r)); x1 ^= x0; }
    TF_R(13) TF_R(15) TF_R(26) TF_R(6)
    x0 += k1; x1 += k2 + 1u;
    TF_R(17) TF_R(29) TF_R(16) TF_R(24)
    x0 += k2; x1 += k0 + 2u;
    TF_R(13) TF_R(15) TF_R(26) TF_R(6)
    x0 += k0; x1 += k1 + 3u;
    TF_R(17) TF_R(29) TF_R(16) TF_R(24)
    x0 += k1; x1 += k2 + 4u;
    TF_R(13) TF_R(15) TF_R(26) TF_R(6)
    x0 += k2; x1 += k0 + 5u;
#undef TF_R
}

__device__ __forceinline__ float cf_uniform(unsigned ka, unsigned kb, unsigned e) {
#if JAX_BITS_MODE == 0
    unsigned x0 = 0u, x1 = e;
    tf2x32(ka, kb, x0, x1);
    unsigned bits = x0 ^ x1;
#else
    unsigned x0 = 0u, x1 = e;
    tf2x32(ka, kb, x0, x1);
    unsigned bits = x0 ^ x1;
#endif
    return __uint_as_float((bits >> 9) | 0x3f800000u) - 1.0f;
}

// ---- packed fp32x2 helpers ----
__device__ __forceinline__ u64 dup2(float s) {
    u64 d; asm("mov.b64 %0, {%1, %1};" : "=l"(d) : "f"(s)); return d;
}
__device__ __forceinline__ u64 pk2(float lo, float hi) {
    u64 d; asm("mov.b64 %0, {%1, %2};" : "=l"(d) : "f"(lo), "f"(hi)); return d;
}
__device__ __forceinline__ float2 unpk(u64 v) {
    float2 r; asm("mov.b64 {%0, %1}, %2;" : "=f"(r.x), "=f"(r.y) : "l"(v)); return r;
}
__device__ __forceinline__ void fma2(u64 &d, u64 a, u64 b) {
    asm("fma.rn.f32x2 %0, %1, %2, %0;" : "+l"(d) : "l"(a), "l"(b));
}
__device__ __forceinline__ void add2(u64 &d, u64 a) {
    asm("add.rn.f32x2 %0, %0, %1;" : "+l"(d) : "l"(a));
}

struct __align__(16) SmemLayout {
    float  w1a[NA][NH1];            // 32 KB  (W1 action rows, natural)
    float  w2s[NH1][NH2];           // 32 KB
    float  w3s[NH2][NA];            // 16 KB
    float2 act_p[TILE_ROWS/2][NA];  // 32 KB  paired: {a[2p][k], a[2p+1][k]}
    float  b1[NH1];
    float  b2[NH2];
    float  b3[NA];
    union {
        struct {
            float2 h1p[TILE_ROWS/2][NH1];   // 64 KB paired h1
            float2 h2p[TILE_ROWS/2][NA];    // 32 KB paired h2
        };
        struct {
            float2 obs_p[TILE_ROWS/2][64];  // 32 KB paired obs chunk
            float  w1o[64][NH1];            // 32 KB W1 obs-row chunk
        };
    };
};  // ~209 KB

extern __shared__ __align__(128) char smem_raw[];

// 8 packed FMAs: two k-steps (m.x={r0k,r1k}, m.y={r0k1,r1k1}) x 4 output cols
#define L1_STEP(ACC_P, M, D00, D01, D02, D03, D10, D11, D12, D13) \
    fma2(ACC_P[0], M.x, D00); fma2(ACC_P[1], M.x, D01);           \
    fma2(ACC_P[2], M.x, D02); fma2(ACC_P[3], M.x, D03);           \
    fma2(ACC_P[0], M.y, D10); fma2(ACC_P[1], M.y, D11);           \
    fma2(ACC_P[2], M.y, D12); fma2(ACC_P[3], M.y, D13);

__global__ void __launch_bounds__(NTHREADS)
ecm_kernel(const float* __restrict__ obs, const float* __restrict__ actions,
           const float* __restrict__ W1,  const float* __restrict__ b1,
           const float* __restrict__ W2,  const float* __restrict__ b2,
           const float* __restrict__ W3,  const float* __restrict__ b3,
           float* __restrict__ out, CfKeys keys)
{
    SmemLayout* s = reinterpret_cast<SmemLayout*>(smem_raw);
    const int tid  = threadIdx.x;
    const int w    = tid >> 5;
    const int lane = tid & 31;
    const int rows0 = blockIdx.x * TILE_ROWS;
    const int wp0   = w * NPAIRS;            // first pair owned by this warp

    // ---- resident weights ----
    {
        const float4* W1f = (const float4*)W1;
        float4* d1 = (float4*)&s->w1a[0][0];
        for (int i = tid; i < NA * NH1 / 4; i += NTHREADS) d1[i] = W1f[256 * 32 + i];
        const float4* W2f = (const float4*)W2;
        float4* d2 = (float4*)&s->w2s[0][0];
        for (int i = tid; i < NH1 * NH2 / 4; i += NTHREADS) d2[i] = W2f[i];
        const float4* W3f = (const float4*)W3;
        float4* d3 = (float4*)&s->w3s[0][0];
        for (int i = tid; i < NH2 * NA / 4; i += NTHREADS) d3[i] = W3f[i];
        for (int i = tid; i < NH1; i += NTHREADS) s->b1[i] = b1[i];
        for (int i = tid; i < NH2; i += NTHREADS) s->b2[i] = b2[i];
        for (int i = tid; i < NA;  i += NTHREADS) s->b3[i] = b3[i];
    }
    __syncthreads();

    // ---- phase A: h1_base = b1 + obs @ W1_obs (packed over row pairs) ----
    u64 h1acc[NPAIRS][4];
    {
        u64 bd0 = dup2(s->b1[lane * 4 + 0]);
        u64 bd1 = dup2(s->b1[lane * 4 + 1]);
        u64 bd2 = dup2(s->b1[lane * 4 + 2]);
        u64 bd3 = dup2(s->b1[lane * 4 + 3]);
        #pragma unroll
        for (int p = 0; p < NPAIRS; ++p) {
            h1acc[p][0] = bd0; h1acc[p][1] = bd1; h1acc[p][2] = bd2; h1acc[p][3] = bd3;
        }
    }
    const float4* obsf = (const float4*)obs;
    const float4* actf = (const float4*)actions;
    const float4* W1f  = (const float4*)W1;

    for (int kc = 0; kc < 4; ++kc) {
        __syncthreads();
        // stage paired obs chunk: obs_p[pair][kk] = {obs[r0][kc*64+kk], obs[r1][kc*64+kk]}
        #pragma unroll
        for (int it = 0; it < 2; ++it) {
            int fl = it * NTHREADS + tid;            // 0..1023: pair(6b) x kq(4b)
            int pr = fl >> 4, k0 = (fl & 15) * 4;
            int r0 = rows0 + pr * 2;
            float4 a = obsf[((size_t)r0 * 256 + kc * 64 + k0) >> 2];
            float4 b = obsf[((size_t)(r0 + 1) * 256 + kc * 64 + k0) >> 2];
            *(float4*)&s->obs_p[pr][k0]     = make_float4(a.x, b.x, a.y, b.y);
            *(float4*)&s->obs_p[pr][k0 + 2] = make_float4(a.z, b.z, a.w, b.w);
        }
        // stage W1 obs-row chunk (natural)
        #pragma unroll
        for (int it = 0; it < 4; ++it) {
            int fl = it * NTHREADS + tid;            // 0..2047
            ((float4*)s->w1o)[fl] = W1f[kc * 2048 + fl];
        }
        __syncthreads();
        #pragma unroll 2
        for (int k4 = 0; k4 < 16; ++k4) {
            #pragma unroll
            for (int ke = 0; ke < 4; ke += 2) {
                int k = k4 * 4 + ke;
                float4 wk0 = *(const float4*)&s->w1o[k][lane * 4];
                float4 wk1 = *(const float4*)&s->w1o[k + 1][lane * 4];
                u64 d00 = dup2(wk0.x), d01 = dup2(wk0.y), d02 = dup2(wk0.z), d03 = dup2(wk0.w);
                u64 d10 = dup2(wk1.x), d11 = dup2(wk1.y), d12 = dup2(wk1.z), d13 = dup2(wk1.w);
                #pragma unroll
                for (int p = 0; p < NPAIRS; ++p) {
                    ulonglong2 m = *(const ulonglong2*)&s->obs_p[wp0 + p][k];
                    L1_STEP(h1acc[p], m, d00, d01, d02, d03, d10, d11, d12, d13)
                }
            }
        }
    }

    // ---- stage true actions (paired) ----
    __syncthreads();
    #pragma unroll
    for (int it = 0; it < 2; ++it) {
        int fl = it * NTHREADS + tid;                // 0..1023
        int pr = fl >> 4, k0 = (fl & 15) * 4;
        int r0 = rows0 + pr * 2;
        float4 a = actf[((size_t)r0 * 64 + k0) >> 2];
        float4 b = actf[((size_t)(r0 + 1) * 64 + k0) >> 2];
        *(float4*)&s->act_p[pr][k0]     = make_float4(a.x, b.x, a.y, b.y);
        *(float4*)&s->act_p[pr][k0 + 2] = make_float4(a.z, b.z, a.w, b.w);
    }
    __syncthreads();

    u64 pw[NPAIRS][2], po[NPAIRS][2];

    for (int pass = 0; pass < 12; ++pass) {
        if (pass >= 2) {
            // per-warp CF generation into this warp's own pairs
            unsigned ka = keys.a[pass - 2], kb = keys.b[pass - 2];
            __syncwarp();
            int lp = lane >> 3;                      // 0..3 local pair
            int k0 = (lane & 7) * 8;                 // 8 ks per lane
            int pr = wp0 + lp;
            unsigned e0 = (unsigned)((rows0 + pr * 2) * 64 + k0);
            #pragma unroll
            for (int i = 0; i < 8; i += 2) {
                float v00 = cf_uniform(ka, kb, e0 + i);
                float v10 = cf_uniform(ka, kb, e0 + i + 64);
                float v01 = cf_uniform(ka, kb, e0 + i + 1);
                float v11 = cf_uniform(ka, kb, e0 + i + 65);
                *(float4*)&s->act_p[pr][k0 + i] = make_float4(v00, v10, v01, v11);
            }
            __syncwarp();
        }

        // ---- layer 1: a1 = relu(h1_base + act @ W1_act) ----
        u64 a1[NPAIRS][4];
        #pragma unroll
        for (int p = 0; p < NPAIRS; ++p) {
            a1[p][0] = h1acc[p][0]; a1[p][1] = h1acc[p][1];
            a1[p][2] = h1acc[p][2]; a1[p][3] = h1acc[p][3];
        }
        if (pass != 1) {
            #pragma unroll 2
            for (int k4 = 0; k4 < 16; ++k4) {
                #pragma unroll
                for (int ke = 0; ke < 4; ke += 2) {
                    int k = k4 * 4 + ke;
                    float4 wk0 = *(const float4*)&s->w1a[k][lane * 4];
                    float4 wk1 = *(const float4*)&s->w1a[k + 1][lane * 4];
                    u64 d00 = dup2(wk0.x), d01 = dup2(wk0.y), d02 = dup2(wk0.z), d03 = dup2(wk0.w);
                    u64 d10 = dup2(wk1.x), d11 = dup2(wk1.y), d12 = dup2(wk1.z), d13 = dup2(wk1.w);
                    #pragma unroll
                    for (int p = 0; p < NPAIRS; ++p) {
                        ulonglong2 m = *(const ulonglong2*)&s->act_p[wp0 + p][k];
                        L1_STEP(a1[p], m, d00, d01, d02, d03, d10, d11, d12, d13)
                    }
                }
            }
        }
        // relu + paired store to h1p
        #pragma unroll
        for (int p = 0; p < NPAIRS; ++p) {
            float2 c0 = unpk(a1[p][0]), c1 = unpk(a1[p][1]);
            float2 c2 = unpk(a1[p][2]), c3 = unpk(a1[p][3]);
            *(float4*)&s->h1p[wp0 + p][lane * 4] =
                make_float4(fmaxf(c0.x, 0.f), fmaxf(c0.y, 0.f), fmaxf(c1.x, 0.f), fmaxf(c1.y, 0.f));
            *(float4*)&s->h1p[wp0 + p][lane * 4 + 2] =
                make_float4(fmaxf(c2.x, 0.f), fmaxf(c2.y, 0.f), fmaxf(c3.x, 0.f), fmaxf(c3.y, 0.f));
        }
        __syncwarp();

        // ---- layer 2: a2 = relu(h1 @ W2 + b2), cols (lane, lane+32) ----
        u64 a2[NPAIRS][2];
        {
            u64 db0 = dup2(s->b2[lane]), db1 = dup2(s->b2[lane + 32]);
            #pragma unroll
            for (int p = 0; p < NPAIRS; ++p) { a2[p][0] = db0; a2[p][1] = db1; }
        }
        #pragma unroll 2
        for (int k4 = 0; k4 < 32; ++k4) {
            #pragma unroll
            for (int ke = 0; ke < 4; ke += 2) {
                int k = k4 * 4 + ke;
                u64 dA0 = dup2(s->w2s[k][lane]),     dB0 = dup2(s->w2s[k][lane + 32]);
                u64 dA1 = dup2(s->w2s[k + 1][lane]), dB1 = dup2(s->w2s[k + 1][lane + 32]);
                #pragma unroll
                for (int p = 0; p < NPAIRS; ++p) {
                    ulonglong2 m = *(const ulonglong2*)&s->h1p[wp0 + p][k];
                    fma2(a2[p][0], m.x, dA0); fma2(a2[p][1], m.x, dB0);
                    fma2(a2[p][0], m.y, dA1); fma2(a2[p][1], m.y, dB1);
                }
            }
        }
        #pragma unroll
        for (int p = 0; p < NPAIRS; ++p) {
            float2 v0 = unpk(a2[p][0]), v1 = unpk(a2[p][1]);
            s->h2p[wp0 + p][lane]      = make_float2(fmaxf(v0.x, 0.f), fmaxf(v0.y, 0.f));
            s->h2p[wp0 + p][lane + 32] = make_float2(fmaxf(v1.x, 0.f), fmaxf(v1.y, 0.f));
        }
        __syncwarp();

        // ---- layer 3: a3 = h2 @ W3 + b3 ----
        u64 a3[NPAIRS][2];
        {
            u64 db0 = dup2(s->b3[lane]), db1 = dup2(s->b3[lane + 32]);
            #pragma unroll
            for (int p = 0; p < NPAIRS; ++p) { a3[p][0] = db0; a3[p][1] = db1; }
        }
        #pragma unroll 2
        for (int k4 = 0; k4 < 16; ++k4) {
            #pragma unroll
            for (int ke = 0; ke < 4; ke += 2) {
                int k = k4 * 4 + ke;
                u64 dA0 = dup2(s->w3s[k][lane]),     dB0 = dup2(s->w3s[k][lane + 32]);
                u64 dA1 = dup2(s->w3s[k + 1][lane]), dB1 = dup2(s->w3s[k + 1][lane + 32]);
                #pragma unroll
                for (int p = 0; p < NPAIRS; ++p) {
                    ulonglong2 m = *(const ulonglong2*)&s->h2p[wp0 + p][k];
                    fma2(a3[p][0], m.x, dA0); fma2(a3[p][1], m.x, dB0);
                    fma2(a3[p][0], m.y, dA1); fma2(a3[p][1], m.y, dB1);
                }
            }
        }
        if (pass == 0) {
            #pragma unroll
            for (int p = 0; p < NPAIRS; ++p) { pw[p][0] = a3[p][0]; pw[p][1] = a3[p][1]; }
        } else if (pass == 1) {
            #pragma unroll
            for (int p = 0; p < NPAIRS; ++p) { po[p][0] = a3[p][0]; po[p][1] = a3[p][1]; }
        } else {
            #pragma unroll
            for (int p = 0; p < NPAIRS; ++p) { add2(po[p][0], a3[p][0]); add2(po[p][1], a3[p][1]); }
        }
    }

    // ---- epilogue: log-softmax + KL, mean over A, per row ----
    const float inv11 = 1.0f / 11.0f;
    #pragma unroll
    for (int p = 0; p < NPAIRS; ++p) {
        float2 pwc0 = unpk(pw[p][0]), pwc1 = unpk(pw[p][1]);
        float2 poc0 = unpk(po[p][0]), poc1 = unpk(po[p][1]);
        #pragma unroll
        for (int h = 0; h < 2; ++h) {
            float p0 = h ? pwc0.y : pwc0.x;
            float p1 = h ? pwc1.y : pwc1.x;
            float q0 = (h ? poc0.y : poc0.x) * inv11;
            float q1 = (h ? poc1.y : poc1.x) * inv11;

            float mw = fmaxf(p0, p1);
            #pragma unroll
            for (int o = 16; o > 0; o >>= 1) mw = fmaxf(mw, __shfl_xor_sync(0xffffffffu, mw, o));
            float sw = expf(p0 - mw) + expf(p1 - mw);
            #pragma unroll
            for (int o = 16; o > 0; o >>= 1) sw += __shfl_xor_sync(0xffffffffu, sw, o);
            float logZw = mw + logf(sw);

            float mq = fmaxf(q0, q1);
            #pragma unroll
            for (int o = 16; o > 0; o >>= 1) mq = fmaxf(mq, __shfl_xor_sync(0xffffffffu, mq, o));
            float sq = expf(q0 - mq) + expf(q1 - mq);
            #pragma unroll
            for (int o = 16; o > 0; o >>= 1) sq += __shfl_xor_sync(0xffffffffu, sq, o);
            float logZq = mq + logf(sq);

            float lq0 = q0 - logZq, lq1 = q1 - logZq;
            float part = expf(lq0) * (lq0 - (p0 - logZw)) + expf(lq1) * (lq1 - (p1 - logZw));
            #pragma unroll
            for (int o = 16; o > 0; o >>= 1) part += __shfl_xor_sync(0xffffffffu, part, o);

            if (lane == 0) out[rows0 + (wp0 + p) * 2 + h] = part * (1.0f / 64.0f);
        }
    }
}

static void compute_cf_keys(CfKeys* kk) {
    const unsigned pa = 0u, pb = 42u;
    for (unsigned j = 0; j < NCF; ++j) {
        unsigned x0 = 0u, x1 = j;
        tf2x32(pa, pb, x0, x1);
        kk->a[j] = x0;
        kk->b[j] = x1;
    }
}

extern "C" void kernel_launch(void* const* d_in, const int* in_sizes, int n_in,
                              void* d_out, int out_size) {
    (void)in_sizes; (void)n_in; (void)out_size;
    const float* obs = (const float*)d_in[0];
    const float* act = (const float*)d_in[1];
    const float* W1  = (const float*)d_in[2];
    const float* b1  = (const float*)d_in[3];
    const float* W2  = (const float*)d_in[4];
    const float* b2  = (const float*)d_in[5];
    const float* W3  = (const float*)d_in[6];
    const float* b3  = (const float*)d_in[7];
    float* out = (float*)d_out;

    CfKeys kk;
    compute_cf_keys(&kk);

    size_t smem = sizeof(SmemLayout);
    cudaFuncSetAttribute(ecm_kernel, cudaFuncAttributeMaxDynamicSharedMemorySize, (int)smem);
    ecm_kernel<<<NTILES, NTHREADS, smem>>>(obs, act, W1, b1, W2, b2, W3, b3, out, kk);
}

// round 16
// speedup vs baseline: 1.6448x; 1.2322x over previous
#include <cuda_runtime.h>
#include <cuda_fp16.h>
#include <mma.h>
#include <cstdint>
using namespace nvcuda;
#define NT 512
#define NCF 10
#define NTILES 1024
#define oW1A_H 0
#define oW1A_L 18432
#define oW2_H 36864
#define oW2_L 54272
#define oW3_H 71680
#define oW3_L 79872
#define oACT_H 88064
#define oACT_L 106496
#define oH1_H 124928
#define oH1_L 159744
#define oH2_H 194560
#define oH2_L 212992
#define SMTOT 231424
#define oW1O_H oH1_H
#define oW1O_L 143360
#define oPW 124928
#define oPO 157696
struct CfKeys { unsigned a[NCF]; unsigned b[NCF]; };
__host__ __device__ __forceinline__ unsigned rotl32(unsigned x,int r){
#if defined(__CUDA_ARCH__)
  return __funnelshift_l(x,x,r);
#else
  return (x<<r)|(x>>(32-r));
#endif
}
__host__ __device__ __forceinline__ void tf2x32(unsigned k0,unsigned k1,unsigned&x0,unsigned&x1){
  unsigned k2=k0^k1^0x1BD11BDAu; x0+=k0; x1+=k1;
#define TF_R(r) {x0+=x1; x1=rotl32(x1,(r)); x1^=x0;}
  TF_R(13)TF_R(15)TF_R(26)TF_R(6) x0+=k1;x1+=k2+1u;
  TF_R(17)TF_R(29)TF_R(16)TF_R(24) x0+=k2;x1+=k0+2u;
  TF_R(13)TF_R(15)TF_R(26)TF_R(6) x0+=k0;x1+=k1+3u;
  TF_R(17)TF_R(29)TF_R(16)TF_R(24) x0+=k1;x1+=k2+4u;
  TF_R(13)TF_R(15)TF_R(26)TF_R(6) x0+=k2;x1+=k0+5u;
#undef TF_R
}
__device__ __forceinline__ float cf_uniform(unsigned ka,unsigned kb,unsigned e){
  unsigned x0=0u,x1=e; tf2x32(ka,kb,x0,x1); unsigned b=x0^x1;
  return __uint_as_float((b>>9)|0x3f800000u)-1.0f;
}
__device__ __forceinline__ void split2(float v,float&hf,float&lf){
  hf=__half2float(__float2half_rn(v)); lf=v-hf;
}
__device__ __forceinline__ uint32_t pkh(float a,float b){
  uint32_t r; asm("{\n\t.reg .b16 x, y;\n\tcvt.rn.f16.f32 x, %1;\n\tcvt.rn.f16.f32 y, %2;\n\tmov.b32 %0, {x, y};\n\t}":"=r"(r):"f"(a),"f"(b)); return r;
}
typedef wmma::fragment<wmma::matrix_a,16,16,16,half,wmma::row_major> FragA;
typedef wmma::fragment<wmma::matrix_b,16,16,16,half,wmma::col_major> FragB;
typedef wmma::fragment<wmma::accumulator,16,16,16,float> FragC;
template<int MI,int NI,int KT,int LDA,int LDB>
__device__ __forceinline__ void wg(FragC* acc,const half* aH,const half* aL,
                                   const half* bH,const half* bL){
  FragA ah[MI],al[MI]; FragB bh,bl;
  for(int kt=0;kt<KT;++kt){
    #pragma unroll
    for(int mi=0;mi<MI;++mi){
      wmma::load_matrix_sync(ah[mi],aH+mi*16*LDA+kt*16,LDA);
      wmma::load_matrix_sync(al[mi],aL+mi*16*LDA+kt*16,LDA);
    }
    #pragma unroll
    for(int ni=0;ni<NI;++ni){
      wmma::load_matrix_sync(bh,bH+ni*16*LDB+kt*16,LDB);
      wmma::load_matrix_sync(bl,bL+ni*16*LDB+kt*16,LDB);
      #pragma unroll
      for(int mi=0;mi<MI;++mi){
        wmma::mma_sync(acc[mi*NI+ni],ah[mi],bh,acc[mi*NI+ni]);
        wmma::mma_sync(acc[mi*NI+ni],ah[mi],bl,acc[mi*NI+ni]);
        wmma::mma_sync(acc[mi*NI+ni],al[mi],bh,acc[mi*NI+ni]);
      }
    }
  }
}
// store acc frag to per-warp scratch, add bias+relu, split-store to dst hi/lo tiles
__device__ __forceinline__ void rback(FragC& c,float* sc,const float* __restrict__ bias,
                                      int row0,int col0,half* dH,half* dL,int ldd,int lane){
  wmma::store_matrix_sync(sc,c,16,wmma::mem_row_major);
  __syncwarp();
  int rr=lane>>1, cb=(lane&1)*8;
  float4 v0=*(float4*)(sc+rr*16+cb);
  float4 v1=*(float4*)(sc+rr*16+cb+4);
  __syncwarp();
  float vv[8]={v0.x,v0.y,v0.z,v0.w,v1.x,v1.y,v1.z,v1.w};
  int row=row0+rr, col=col0+cb;
  uint32_t* pH=(uint32_t*)(dH+row*ldd+col);
  uint32_t* pL=(uint32_t*)(dL+row*ldd+col);
  #pragma unroll
  for(int j=0;j<4;++j){
    float a=fmaxf(vv[2*j]+bias[col+2*j],0.f);
    float b=fmaxf(vv[2*j+1]+bias[col+2*j+1],0.f);
    float hA,lA,hB,lB; split2(a,hA,lA); split2(b,hB,lB);
    pH[j]=pkh(hA,hB); pL[j]=pkh(lA,lB);
  }
}
extern __shared__ __align__(1024) char smemr[];
__global__ void __launch_bounds__(NT)
ecm_wmma(const float* __restrict__ obs,const float* __restrict__ actions,
  const float* __restrict__ W1,const float* __restrict__ b1,
  const float* __restrict__ W2,const float* __restrict__ b2,
  const float* __restrict__ W3,const float* __restrict__ b3,
  float* __restrict__ out,CfKeys keys)
{
  char* sm=smemr;
  const int tid=threadIdx.x,w=tid>>5,lane=tid&31;
  const int wm=w&3,wn=w>>2;
  const int rows0=blockIdx.x*128;
  half* W1AH=(half*)(sm+oW1A_H); half* W1AL=(half*)(sm+oW1A_L);
  half* W2H=(half*)(sm+oW2_H);   half* W2L=(half*)(sm+oW2_L);
  half* W3H=(half*)(sm+oW3_H);   half* W3L=(half*)(sm+oW3_L);
  half* ACTH=(half*)(sm+oACT_H); half* ACTL=(half*)(sm+oACT_L);
  half* H1H=(half*)(sm+oH1_H);   half* H1L=(half*)(sm+oH1_L);
  half* H2H=(half*)(sm+oH2_H);   half* H2L=(half*)(sm+oH2_L);
  half* W1OH=(half*)(sm+oW1O_H); half* W1OL=(half*)(sm+oW1O_L);
  // resident weights (split fp16): B tiles stored [n][k], col-major for wmma
  for(int it=0;it<16;++it){ int x=it*NT+tid,n=x&127,k=x>>7;
    float hf,lf; split2(W1[(256+k)*128+n],hf,lf);
    W1AH[n*72+k]=__float2half_rn(hf); W1AL[n*72+k]=__float2half_rn(lf); }
  for(int it=0;it<16;++it){ int x=it*NT+tid,n=x&63,k=x>>6;
    float hf,lf; split2(W2[k*64+n],hf,lf);
    W2H[n*136+k]=__float2half_rn(hf); W2L[n*136+k]=__float2half_rn(lf); }
  for(int it=0;it<8;++it){ int x=it*NT+tid,n=x&63,k=x>>6;
    float hf,lf; split2(W3[k*64+n],hf,lf);
    W3H[n*64+k]=__float2half_rn(hf); W3L[n*64+k]=__float2half_rn(lf); }
  // phase A: h1base = obs @ W1_obs (bias b1 added later at L1 readback)
  FragC h1b[4];
  #pragma unroll
  for(int i=0;i<4;++i) wmma::fill_fragment(h1b[i],0.f);
  for(int kc=0;kc<4;++kc){
    __syncthreads();
    for(int it=0;it<16;++it){ int x=it*NT+tid,k=x&63,r=x>>6;
      float hf,lf; split2(obs[(size_t)(rows0+r)*256+kc*64+k],hf,lf);
      ACTH[r*72+k]=__float2half_rn(hf); ACTL[r*72+k]=__float2half_rn(lf); }
    for(int it=0;it<16;++it){ int x=it*NT+tid,n=x&127,k=x>>7;
      float hf,lf; split2(W1[(kc*64+k)*128+n],hf,lf);
      W1OH[n*72+k]=__float2half_rn(hf); W1OL[n*72+k]=__float2half_rn(lf); }
    __syncthreads();
    wg<2,2,4,72,72>(h1b,ACTH+wm*32*72,ACTL+wm*32*72,W1OH+wn*32*72,W1OL+wn*32*72);
  }
  FragC pw[2],po[2];
  for(int pass=0;pass<12;++pass){
    __syncthreads();   // all warps past prior GEMMs before ACT restage
    if(pass==0){
      int r=tid>>2,kb=(tid&3)*16;
      const float4* af=(const float4*)(actions+(size_t)(rows0+r)*64+kb);
      #pragma unroll
      for(int q=0;q<4;++q){
        float4 v=af[q];
        float h0,l0,h1,l1,h2,l2,h3,l3;
        split2(v.x,h0,l0); split2(v.y,h1,l1); split2(v.z,h2,l2); split2(v.w,h3,l3);
        *(uint32_t*)(ACTH+r*72+kb+q*4)  =pkh(h0,h1);
        *(uint32_t*)(ACTH+r*72+kb+q*4+2)=pkh(h2,h3);
        *(uint32_t*)(ACTL+r*72+kb+q*4)  =pkh(l0,l1);
        *(uint32_t*)(ACTL+r*72+kb+q*4+2)=pkh(l2,l3);
      }
    } else if(pass>=2){
      unsigned ka=keys.a[pass-2],kb_=keys.b[pass-2];
      int r=tid>>2,kb=(tid&3)*16;
      unsigned e0=(unsigned)((rows0+r)*64+kb);
      #pragma unroll 2
      for(int i=0;i<16;i+=2){
        float v0=cf_uniform(ka,kb_,e0+i),v1=cf_uniform(ka,kb_,e0+i+1);
        float h0,l0,h1,l1; split2(v0,h0,l0); split2(v1,h1,l1);
        *(uint32_t*)(ACTH+r*72+kb+i)=pkh(h0,h1);
        *(uint32_t*)(ACTL+r*72+kb+i)=pkh(l0,l1);
      }
    }
    __syncthreads();
    // L1: acc = h1base (+ act@W1a)
    FragC acc[4];
    #pragma unroll
    for(int i=0;i<4;++i)
      #pragma unroll
      for(int e=0;e<acc[0].num_elements;++e) acc[i].x[e]=h1b[i].x[e];
    if(pass!=1)
      wg<2,2,4,72,72>(acc,ACTH+wm*32*72,ACTL+wm*32*72,W1AH+wn*32*72,W1AL+wn*32*72);
    // readback: relu(x+b1) -> H1 split tiles; per-warp scratch in free H2 region
    {
      float* sc=(float*)(sm+oH2_H)+w*256;
      #pragma unroll
      for(int mi=0;mi<2;++mi)
        #pragma unroll
        for(int ni=0;ni<2;++ni)
          rback(acc[mi*2+ni],sc,b1,wm*32+mi*16,wn*32+ni*16,H1H,H1L,136,lane);
    }
    __syncthreads();
    // L2: h2 = relu(h1@W2 + b2)
    FragC a2[2];
    wmma::fill_fragment(a2[0],0.f); wmma::fill_fragment(a2[1],0.f);
    wg<2,1,8,136,136>(a2,H1H+wm*32*136,H1L+wm*32*136,W2H+wn*16*136,W2L+wn*16*136);
    {
      float* sc=(float*)(sm+oACT_H)+w*256;   // ACT free after L1
      #pragma unroll
      for(int mi=0;mi<2;++mi)
        rback(a2[mi],sc,b2,wm*32+mi*16,wn*16,H2H,H2L,72,lane);
    }
    __syncthreads();
    // L3: logits (bias b3 deferred to final epilogue)
    FragC a3[2];
    wmma::fill_fragment(a3[0],0.f); wmma::fill_fragment(a3[1],0.f);
    wg<2,1,4,72,64>(a3,H2H+wm*32*72,H2L+wm*32*72,W3H+wn*16*64,W3L+wn*16*64);
    if(pass==0){
      #pragma unroll
      for(int i=0;i<2;++i)
        #pragma unroll
        for(int e=0;e<a3[0].num_elements;++e) pw[i].x[e]=a3[i].x[e];
    } else if(pass==1){
      #pragma unroll
      for(int i=0;i<2;++i)
        #pragma unroll
        for(int e=0;e<a3[0].num_elements;++e) po[i].x[e]=a3[i].x[e];
    } else {
      #pragma unroll
      for(int i=0;i<2;++i)
        #pragma unroll
        for(int e=0;e<a3[0].num_elements;++e) po[i].x[e]+=a3[i].x[e];
    }
  }
  __syncthreads();
  float* pwb=(float*)(sm+oPW); float* pob=(float*)(sm+oPO);
  #pragma unroll
  for(int mi=0;mi<2;++mi){
    wmma::store_matrix_sync(pwb+(wm*32+mi*16)*64+wn*16,pw[mi],64,wmma::mem_row_major);
    wmma::store_matrix_sync(pob+(wm*32+mi*16)*64+wn*16,po[mi],64,wmma::mem_row_major);
  }
  __syncthreads();
  {
    const float inv11=1.0f/11.0f;
    int row=tid>>2,cb=(tid&3)*16;
    float pv[16],qv[16];
    #pragma unroll
    for(int j=0;j<16;++j){
      float bb=b3[cb+j];
      pv[j]=pwb[row*64+cb+j]+bb;
      qv[j]=pob[row*64+cb+j]*inv11+bb;
    }
    float mw=-1e30f,mq=-1e30f;
    #pragma unroll
    for(int j=0;j<16;++j){ mw=fmaxf(mw,pv[j]); mq=fmaxf(mq,qv[j]); }
    mw=fmaxf(mw,__shfl_xor_sync(0xffffffffu,mw,1)); mw=fmaxf(mw,__shfl_xor_sync(0xffffffffu,mw,2));
    mq=fmaxf(mq,__shfl_xor_sync(0xffffffffu,mq,1)); mq=fmaxf(mq,__shfl_xor_sync(0xffffffffu,mq,2));
    float sw=0.f,sq=0.f;
    #pragma unroll
    for(int j=0;j<16;++j){ sw+=expf(pv[j]-mw); sq+=expf(qv[j]-mq); }
    sw+=__shfl_xor_sync(0xffffffffu,sw,1); sw+=__shfl_xor_sync(0xffffffffu,sw,2);
    sq+=__shfl_xor_sync(0xffffffffu,sq,1); sq+=__shfl_xor_sync(0xffffffffu,sq,2);
    float lZw=mw+logf(sw),lZq=mq+logf(sq),kl=0.f;
    #pragma unroll
    for(int j=0;j<16;++j){ float lq=qv[j]-lZq,lp=pv[j]-lZw; kl+=expf(lq)*(lq-lp); }
    kl+=__shfl_xor_sync(0xffffffffu,kl,1); kl+=__shfl_xor_sync(0xffffffffu,kl,2);
    if((tid&3)==0) out[rows0+row]=kl*(1.0f/64.0f);
  }
}
static void compute_cf_keys(CfKeys* kk){
  for(unsigned j=0;j<NCF;++j){
    unsigned x0=0u,x1=j; tf2x32(0u,42u,x0,x1);
    kk->a[j]=x0; kk->b[j]=x1;
  }
}
extern "C" void kernel_launch(void* const* d_in,const int* in_sizes,int n_in,
                              void* d_out,int out_size){
  (void)in_sizes;(void)n_in;(void)out_size;
  CfKeys kk; compute_cf_keys(&kk);
  cudaFuncSetAttribute(ecm_wmma,cudaFuncAttributeMaxDynamicSharedMemorySize,SMTOT);
  ecm_wmma<<<NTILES,NT,SMTOT>>>((const float*)d_in[0],(const float*)d_in[1],
    (const float*)d_in[2],(const float*)d_in[3],(const float*)d_in[4],
    (const float*)d_in[5],(const float*)d_in[6],(const float*)d_in[7],
    (float*)d_out,kk);
}

// round 17
// speedup vs baseline: 1.7281x; 1.0506x over previous
#include <cuda_runtime.h>
#include <cuda_fp16.h>
#include <mma.h>
#include <cstdint>
using namespace nvcuda;
#define NT 512
#define NCF 10
#define NTILES 1024
#define oW1A_H 0
#define oW1A_L 18432
#define oW2_H 36864
#define oW2_L 54272
#define oW3_H 71680
#define oW3_L 79872
#define oACT_H 88064
#define oACT_L 106496
#define oH1_H 124928
#define oH1_L 159744
#define oH2_H 194560
#define oH2_L 212992
#define SMTOT 231424
#define oW1O_H oH1_H
#define oW1O_L 143360
#define oPW 124928
#define oPO 157696
struct CfKeys { unsigned a[NCF]; unsigned b[NCF]; };
__host__ __device__ __forceinline__ unsigned rotl32(unsigned x,int r){
#if defined(__CUDA_ARCH__)
  return __funnelshift_l(x,x,r);
#else
  return (x<<r)|(x>>(32-r));
#endif
}
__host__ __device__ __forceinline__ void tf2x32(unsigned k0,unsigned k1,unsigned&x0,unsigned&x1){
  unsigned k2=k0^k1^0x1BD11BDAu; x0+=k0; x1+=k1;
#define TF_R(r) {x0+=x1; x1=rotl32(x1,(r)); x1^=x0;}
  TF_R(13)TF_R(15)TF_R(26)TF_R(6) x0+=k1;x1+=k2+1u;
  TF_R(17)TF_R(29)TF_R(16)TF_R(24) x0+=k2;x1+=k0+2u;
  TF_R(13)TF_R(15)TF_R(26)TF_R(6) x0+=k0;x1+=k1+3u;
  TF_R(17)TF_R(29)TF_R(16)TF_R(24) x0+=k1;x1+=k2+4u;
  TF_R(13)TF_R(15)TF_R(26)TF_R(6) x0+=k2;x1+=k0+5u;
#undef TF_R
}
__device__ __forceinline__ float cf_uniform(unsigned ka,unsigned kb,unsigned e){
  unsigned x0=0u,x1=e; tf2x32(ka,kb,x0,x1); unsigned b=x0^x1;
  return __uint_as_float((b>>9)|0x3f800000u)-1.0f;
}
__device__ __forceinline__ void split2(float v,float&hf,float&lf){
  hf=__half2float(__float2half_rn(v)); lf=v-hf;
}
__device__ __forceinline__ uint32_t pkh(float a,float b){
  uint32_t r; asm("{\n\t.reg .b16 x, y;\n\tcvt.rn.f16.f32 x, %1;\n\tcvt.rn.f16.f32 y, %2;\n\tmov.b32 %0, {x, y};\n\t}":"=r"(r):"f"(a),"f"(b)); return r;
}
typedef wmma::fragment<wmma::matrix_a,16,16,16,half,wmma::row_major> FragA;
typedef wmma::fragment<wmma::matrix_b,16,16,16,half,wmma::col_major> FragB;
typedef wmma::fragment<wmma::accumulator,16,16,16,float> FragC;
template<int MI,int NI,int KT,int LDA,int LDB>
__device__ __forceinline__ void wg(FragC* acc,const half* aH,const half* aL,
                                   const half* bH,const half* bL){
  FragA ah[MI],al[MI]; FragB bh,bl;
  for(int kt=0;kt<KT;++kt){
    #pragma unroll
    for(int mi=0;mi<MI;++mi){
      wmma::load_matrix_sync(ah[mi],aH+mi*16*LDA+kt*16,LDA);
      wmma::load_matrix_sync(al[mi],aL+mi*16*LDA+kt*16,LDA);
    }
    #pragma unroll
    for(int ni=0;ni<NI;++ni){
      wmma::load_matrix_sync(bh,bH+ni*16*LDB+kt*16,LDB);
      wmma::load_matrix_sync(bl,bL+ni*16*LDB+kt*16,LDB);
      #pragma unroll
      for(int mi=0;mi<MI;++mi){
        wmma::mma_sync(acc[mi*NI+ni],ah[mi],bh,acc[mi*NI+ni]);
        wmma::mma_sync(acc[mi*NI+ni],ah[mi],bl,acc[mi*NI+ni]);
        wmma::mma_sync(acc[mi*NI+ni],al[mi],bh,acc[mi*NI+ni]);
      }
    }
  }
}
__device__ __forceinline__ void rback(FragC& c,float* sc,const float* __restrict__ bias,
                                      int row0,int col0,half* dH,half* dL,int ldd,int lane){
  wmma::store_matrix_sync(sc,c,16,wmma::mem_row_major);
  __syncwarp();
  int rr=lane>>1, cb=(lane&1)*8;
  float4 v0=*(float4*)(sc+rr*16+cb);
  float4 v1=*(float4*)(sc+rr*16+cb+4);
  __syncwarp();
  float vv[8]={v0.x,v0.y,v0.z,v0.w,v1.x,v1.y,v1.z,v1.w};
  int row=row0+rr, col=col0+cb;
  uint32_t* pH=(uint32_t*)(dH+row*ldd+col);
  uint32_t* pL=(uint32_t*)(dL+row*ldd+col);
  #pragma unroll
  for(int j=0;j<4;++j){
    float a=fmaxf(vv[2*j]+bias[col+2*j],0.f);
    float b=fmaxf(vv[2*j+1]+bias[col+2*j+1],0.f);
    float hA,lA,hB,lB; split2(a,hA,lA); split2(b,hB,lB);
    pH[j]=pkh(hA,hB); pL[j]=pkh(lA,lB);
  }
}
extern __shared__ __align__(1024) char smemr[];
__global__ void __launch_bounds__(NT)
ecm_wmma(const float* __restrict__ obs,const float* __restrict__ actions,
  const float* __restrict__ W1,const float* __restrict__ b1,
  const float* __restrict__ W2,const float* __restrict__ b2,
  const float* __restrict__ W3,const float* __restrict__ b3,
  float* __restrict__ out,CfKeys keys)
{
  char* sm=smemr;
  const int tid=threadIdx.x,w=tid>>5,lane=tid&31;
  const int wm=w&3,wn=w>>2;
  const int rows0=blockIdx.x*128;
  half* W1AH=(half*)(sm+oW1A_H); half* W1AL=(half*)(sm+oW1A_L);
  half* W2H=(half*)(sm+oW2_H);   half* W2L=(half*)(sm+oW2_L);
  half* W3H=(half*)(sm+oW3_H);   half* W3L=(half*)(sm+oW3_L);
  half* ACTH=(half*)(sm+oACT_H); half* ACTL=(half*)(sm+oACT_L);
  half* H1H=(half*)(sm+oH1_H);   half* H1L=(half*)(sm+oH1_L);
  half* H2H=(half*)(sm+oH2_H);   half* H2L=(half*)(sm+oH2_L);
  half* W1OH=(half*)(sm+oW1O_H); half* W1OL=(half*)(sm+oW1O_L);
  for(int it=0;it<16;++it){ int x=it*NT+tid,n=x&127,k=x>>7;
    float hf,lf; split2(W1[(256+k)*128+n],hf,lf);
    W1AH[n*72+k]=__float2half_rn(hf); W1AL[n*72+k]=__float2half_rn(lf); }
  for(int it=0;it<16;++it){ int x=it*NT+tid,n=x&63,k=x>>6;
    float hf,lf; split2(W2[k*64+n],hf,lf);
    W2H[n*136+k]=__float2half_rn(hf); W2L[n*136+k]=__float2half_rn(lf); }
  for(int it=0;it<8;++it){ int x=it*NT+tid,n=x&63,k=x>>6;
    float hf,lf; split2(W3[k*64+n],hf,lf);
    W3H[n*64+k]=__float2half_rn(hf); W3L[n*64+k]=__float2half_rn(lf); }
  FragC h1b[4];
  #pragma unroll
  for(int i=0;i<4;++i) wmma::fill_fragment(h1b[i],0.f);
  for(int kc=0;kc<4;++kc){
    __syncthreads();
    for(int it=0;it<16;++it){ int x=it*NT+tid,k=x&63,r=x>>6;
      float hf,lf; split2(obs[(size_t)(rows0+r)*256+kc*64+k],hf,lf);
      ACTH[r*72+k]=__float2half_rn(hf); ACTL[r*72+k]=__float2half_rn(lf); }
    for(int it=0;it<16;++it){ int x=it*NT+tid,n=x&127,k=x>>7;
      float hf,lf; split2(W1[(kc*64+k)*128+n],hf,lf);
      W1OH[n*72+k]=__float2half_rn(hf); W1OL[n*72+k]=__float2half_rn(lf); }
    __syncthreads();
    wg<2,2,4,72,72>(h1b,ACTH+wm*32*72,ACTL+wm*32*72,W1OH+wn*32*72,W1OL+wn*32*72);
  }
  __syncthreads();   // obs reads done before ACT overwrite
  {  // stage true actions once
    int r=tid>>2,kb=(tid&3)*16;
    const float4* af=(const float4*)(actions+(size_t)(rows0+r)*64+kb);
    #pragma unroll
    for(int q=0;q<4;++q){
      float4 v=af[q];
      float h0,l0,h1,l1,h2,l2,h3,l3;
      split2(v.x,h0,l0); split2(v.y,h1,l1); split2(v.z,h2,l2); split2(v.w,h3,l3);
      *(uint32_t*)(ACTH+r*72+kb+q*4)  =pkh(h0,h1);
      *(uint32_t*)(ACTH+r*72+kb+q*4+2)=pkh(h2,h3);
      *(uint32_t*)(ACTL+r*72+kb+q*4)  =pkh(l0,l1);
      *(uint32_t*)(ACTL+r*72+kb+q*4+2)=pkh(l2,l3);
    }
  }
  __syncthreads();
  FragC pw[2],po[2];
  const int gr=tid>>2, gkb=(tid&3)*16;        // CF row/col assignment
  for(int pass=0;pass<12;++pass){
    // ---- L1 ----
    FragC acc[4];
    #pragma unroll
    for(int i=0;i<4;++i)
      #pragma unroll
      for(int e=0;e<acc[0].num_elements;++e) acc[i].x[e]=h1b[i].x[e];
    if(pass!=1)
      wg<2,2,4,72,72>(acc,ACTH+wm*32*72,ACTL+wm*32*72,W1AH+wn*32*72,W1AL+wn*32*72);
    {
      float* sc=(float*)(sm+oH2_H)+w*256;
      #pragma unroll
      for(int mi=0;mi<2;++mi)
        #pragma unroll
        for(int ni=0;ni<2;++ni)
          rback(acc[mi*2+ni],sc,b1,wm*32+mi*16,wn*32+ni*16,H1H,H1L,136,lane);
    }
    __syncthreads();     // S1
    // gen first 8 CF values for pass+1 into registers (overlaps L2)
    const int dogen=(pass>=1&&pass<=10);
    unsigned g0[4],g1[4];
    unsigned ka=0,kb_=0,e0=0;
    if(dogen){
      ka=keys.a[pass-1]; kb_=keys.b[pass-1];
      e0=(unsigned)((rows0+gr)*64+gkb);
      #pragma unroll
      for(int i=0;i<4;++i){
        float v0=cf_uniform(ka,kb_,e0+2*i),v1=cf_uniform(ka,kb_,e0+2*i+1);
        float h0,l0,h1,l1; split2(v0,h0,l0); split2(v1,h1,l1);
        g0[i]=pkh(h0,h1); g1[i]=pkh(l0,l1);
      }
    }
    // ---- L2 ----
    FragC a2[2];
    wmma::fill_fragment(a2[0],0.f); wmma::fill_fragment(a2[1],0.f);
    wg<2,1,8,136,136>(a2,H1H+wm*32*136,H1L+wm*32*136,W2H+wn*16*136,W2L+wn*16*136);
    {
      float* sc=(float*)(sm+oACT_H)+w*256;
      #pragma unroll
      for(int mi=0;mi<2;++mi)
        rback(a2[mi],sc,b2,wm*32+mi*16,wn*16,H2H,H2L,72,lane);
    }
    __syncthreads();     // S2
    // flush first 8, gen+write second 8 (overlaps L3; ACT untouched by L3)
    if(dogen){
      #pragma unroll
      for(int i=0;i<4;++i){
        *(uint32_t*)(ACTH+gr*72+gkb+2*i)=g0[i];
        *(uint32_t*)(ACTL+gr*72+gkb+2*i)=g1[i];
      }
      #pragma unroll
      for(int i=0;i<4;++i){
        float v0=cf_uniform(ka,kb_,e0+8+2*i),v1=cf_uniform(ka,kb_,e0+9+2*i);
        float h0,l0,h1,l1; split2(v0,h0,l0); split2(v1,h1,l1);
        *(uint32_t*)(ACTH+gr*72+gkb+8+2*i)=pkh(h0,h1);
        *(uint32_t*)(ACTL+gr*72+gkb+8+2*i)=pkh(l0,l1);
      }
    }
    // ---- L3 ----
    FragC a3[2];
    wmma::fill_fragment(a3[0],0.f); wmma::fill_fragment(a3[1],0.f);
    wg<2,1,4,72,64>(a3,H2H+wm*32*72,H2L+wm*32*72,W3H+wn*16*64,W3L+wn*16*64);
    if(pass==0){
      #pragma unroll
      for(int i=0;i<2;++i)
        #pragma unroll
        for(int e=0;e<a3[0].num_elements;++e) pw[i].x[e]=a3[i].x[e];
    } else if(pass==1){
      #pragma unroll
      for(int i=0;i<2;++i)
        #pragma unroll
        for(int e=0;e<a3[0].num_elements;++e) po[i].x[e]=a3[i].x[e];
    } else {
      #pragma unroll
      for(int i=0;i<2;++i)
        #pragma unroll
        for(int e=0;e<a3[0].num_elements;++e) po[i].x[e]+=a3[i].x[e];
    }
    __syncthreads();     // S3: ACT/H2 handoff to next pass
  }
  float* pwb=(float*)(sm+oPW); float* pob=(float*)(sm+oPO);
  #pragma unroll
  for(int mi=0;mi<2;++mi){
    wmma::store_matrix_sync(pwb+(wm*32+mi*16)*64+wn*16,pw[mi],64,wmma::mem_row_major);
    wmma::store_matrix_sync(pob+(wm*32+mi*16)*64+wn*16,po[mi],64,wmma::mem_row_major);
  }
  __syncthreads();
  {
    const float inv11=1.0f/11.0f;
    int row=tid>>2,cb=(tid&3)*16;
    float pv[16],qv[16];
    #pragma unroll
    for(int j=0;j<16;++j){
      float bb=b3[cb+j];
      pv[j]=pwb[row*64+cb+j]+bb;
      qv[j]=pob[row*64+cb+j]*inv11+bb;
    }
    float mw=-1e30f,mq=-1e30f;
    #pragma unroll
    for(int j=0;j<16;++j){ mw=fmaxf(mw,pv[j]); mq=fmaxf(mq,qv[j]); }
    mw=fmaxf(mw,__shfl_xor_sync(0xffffffffu,mw,1)); mw=fmaxf(mw,__shfl_xor_sync(0xffffffffu,mw,2));
    mq=fmaxf(mq,__shfl_xor_sync(0xffffffffu,mq,1)); mq=fmaxf(mq,__shfl_xor_sync(0xffffffffu,mq,2));
    float sw=0.f,sq=0.f;
    #pragma unroll
    for(int j=0;j<16;++j){ sw+=__expf(pv[j]-mw); sq+=__expf(qv[j]-mq); }
    sw+=__shfl_xor_sync(0xffffffffu,sw,1); sw+=__shfl_xor_sync(0xffffffffu,sw,2);
    sq+=__shfl_xor_sync(0xffffffffu,sq,1); sq+=__shfl_xor_sync(0xffffffffu,sq,2);
    float lZw=mw+__logf(sw),lZq=mq+__logf(sq),kl=0.f;
    #pragma unroll
    for(int j=0;j<16;++j){ float lq=qv[j]-lZq,lp=pv[j]-lZw; kl+=__expf(lq)*(lq-lp); }
    kl+=__shfl_xor_sync(0xffffffffu,kl,1); kl+=__shfl_xor_sync(0xffffffffu,kl,2);
    if((tid&3)==0) out[rows0+row]=kl*(1.0f/64.0f);
  }
}
static void compute_cf_keys(CfKeys* kk){
  for(unsigned j=0;j<NCF;++j){
    unsigned x0=0u,x1=j; tf2x32(0u,42u,x0,x1);
    kk->a[j]=x0; kk->b[j]=x1;
  }
}
extern "C" void kernel_launch(void* const* d_in,const int* in_sizes,int n_in,
                              void* d_out,int out_size){
  (void)in_sizes;(void)n_in;(void)out_size;
  CfKeys kk; compute_cf_keys(&kk);
  cudaFuncSetAttribute(ecm_wmma,cudaFuncAttributeMaxDynamicSharedMemorySize,SMTOT);
  ecm_wmma<<<NTILES,NT,SMTOT>>>((const float*)d_in[0],(const float*)d_in[1],
    (const float*)d_in[2],(const float*)d_in[3],(const float*)d_in[4],
    (const float*)d_in[5],(const float*)d_in[6],(const float*)d_in[7],
    (float*)d_out,kk);
}